// round 2
// baseline (speedup 1.0000x reference)
#include <cuda_runtime.h>
#include <cuda_bf16.h>
#include <cstdint>

// Problem constants (fixed shapes)
#define SOM_M   128
#define SOM_N   128
#define COMPS   16384     // SOM_M * SOM_N
#define BS      4096
#define DIM     768
#define NITER_F 1000.0f
#define ALPHA_F 0.3f
#define SIGMA_F 64.0f     // max(M,N)/2

// Device scratch (no allocations allowed in kernel_launch)
__device__ float              g_wn[COMPS];
__device__ unsigned long long g_key[BS];
__device__ int                g_bmu[BS];

// ---------------------------------------------------------------------------
// monotone ordered encoding of float for integer max-compare
__device__ __forceinline__ unsigned ordf(float f) {
    unsigned u = __float_as_uint(f);
    return (u & 0x80000000u) ? ~u : (u | 0x80000000u);
}

// ---------------------------------------------------------------------------
// K0a: zero the argmax keys
__global__ void zero_keys_kernel() {
    int t = blockIdx.x * blockDim.x + threadIdx.x;
    if (t < BS) g_key[t] = 0ull;
}

// K0b: wn[c] = ||w_c||^2  (one warp per row)
__global__ void wn_kernel(const float* __restrict__ W) {
    int warp = threadIdx.x >> 5;
    int lane = threadIdx.x & 31;
    int c = blockIdx.x * 8 + warp;
    if (c >= COMPS) return;
    const float* row = &W[(size_t)c * DIM];
    float s = 0.f;
    #pragma unroll 6
    for (int i = lane; i < DIM; i += 32) {
        float v = row[i];
        s = fmaf(v, v, s);
    }
    #pragma unroll
    for (int o = 16; o > 0; o >>= 1) s += __shfl_xor_sync(0xFFFFFFFFu, s, o);
    if (lane == 0) g_wn[c] = s;
}

// ---------------------------------------------------------------------------
// K1: BMU search. Tiled 64b x 64c x 16k dot-product with argmax epilogue.
// score[b,c] = x_b . w_c - 0.5*wn[c];  argmax_c score == argmin_c d2.
__global__ __launch_bounds__(256) void bmu_kernel(const float* __restrict__ X,
                                                  const float* __restrict__ W) {
    __shared__ float xs[16][64];   // [k][b]
    __shared__ float ws[16][64];   // [k][c]
    __shared__ unsigned long long red[64][16];

    const int t  = threadIdx.x;
    const int c0 = blockIdx.x * 64;
    const int b0 = blockIdx.y * 64;
    const int tx = t & 15;          // c sub-tile
    const int ty = t >> 4;          // b sub-tile

    const int lrow = t >> 2;        // 0..63
    const int lcol = (t & 3) * 4;   // 0,4,8,12

    float acc[4][4];
    #pragma unroll
    for (int i = 0; i < 4; i++)
        #pragma unroll
        for (int j = 0; j < 4; j++) acc[i][j] = 0.f;

    for (int k0 = 0; k0 < DIM; k0 += 16) {
        float4 av = *(const float4*)&X[(size_t)(b0 + lrow) * DIM + k0 + lcol];
        float4 bv = *(const float4*)&W[(size_t)(c0 + lrow) * DIM + k0 + lcol];
        __syncthreads();
        xs[lcol + 0][lrow] = av.x; xs[lcol + 1][lrow] = av.y;
        xs[lcol + 2][lrow] = av.z; xs[lcol + 3][lrow] = av.w;
        ws[lcol + 0][lrow] = bv.x; ws[lcol + 1][lrow] = bv.y;
        ws[lcol + 2][lrow] = bv.z; ws[lcol + 3][lrow] = bv.w;
        __syncthreads();
        #pragma unroll
        for (int k = 0; k < 16; k++) {
            float4 a = *(const float4*)&xs[k][ty * 4];
            float4 b = *(const float4*)&ws[k][tx * 4];
            acc[0][0] = fmaf(a.x, b.x, acc[0][0]);
            acc[0][1] = fmaf(a.x, b.y, acc[0][1]);
            acc[0][2] = fmaf(a.x, b.z, acc[0][2]);
            acc[0][3] = fmaf(a.x, b.w, acc[0][3]);
            acc[1][0] = fmaf(a.y, b.x, acc[1][0]);
            acc[1][1] = fmaf(a.y, b.y, acc[1][1]);
            acc[1][2] = fmaf(a.y, b.z, acc[1][2]);
            acc[1][3] = fmaf(a.y, b.w, acc[1][3]);
            acc[2][0] = fmaf(a.z, b.x, acc[2][0]);
            acc[2][1] = fmaf(a.z, b.y, acc[2][1]);
            acc[2][2] = fmaf(a.z, b.z, acc[2][2]);
            acc[2][3] = fmaf(a.z, b.w, acc[2][3]);
            acc[3][0] = fmaf(a.w, b.x, acc[3][0]);
            acc[3][1] = fmaf(a.w, b.y, acc[3][1]);
            acc[3][2] = fmaf(a.w, b.z, acc[3][2]);
            acc[3][3] = fmaf(a.w, b.w, acc[3][3]);
        }
    }

    // epilogue: per-thread argmax over its 4 c, then block reduce, then atomic
    float wnj[4];
    #pragma unroll
    for (int j = 0; j < 4; j++) wnj[j] = g_wn[c0 + tx * 4 + j];

    #pragma unroll
    for (int i = 0; i < 4; i++) {
        unsigned long long best = 0ull;
        #pragma unroll
        for (int j = 0; j < 4; j++) {
            float score = acc[i][j] - 0.5f * wnj[j];
            unsigned cidx = (unsigned)(c0 + tx * 4 + j);
            unsigned long long key =
                ((unsigned long long)ordf(score) << 32) | (0xFFFFFFFFu - cidx);
            if (key > best) best = key;
        }
        red[ty * 4 + i][tx] = best;
    }
    __syncthreads();
    if (t < 64) {
        unsigned long long m = red[t][0];
        #pragma unroll
        for (int j = 1; j < 16; j++) {
            unsigned long long v = red[t][j];
            if (v > m) m = v;
        }
        atomicMax(&g_key[b0 + t], m);
    }
}

// decode packed keys -> bmu indices
__global__ void decode_kernel() {
    int t = blockIdx.x * blockDim.x + threadIdx.x;
    if (t < BS)
        g_bmu[t] = (int)(0xFFFFFFFFu - (unsigned)(g_key[t] & 0xFFFFFFFFull));
}

// ---------------------------------------------------------------------------
// K2: update. One CTA owns 16 c-rows x full 768 d. Loop over b in chunks of 8.
// lr[b,c] computed once per (b,c) from bmu[b]; acc[c][d] += lr*x[b][d].
// out[c,d] = w[c,d]*(1 - S[c]) + acc[c][d].
#define CB  16
#define BCH 8
#define UPD_THREADS 192   // 192*4 = 768 d columns

__global__ __launch_bounds__(UPD_THREADS) void update_kernel(
    const float* __restrict__ X, const float* __restrict__ W,
    const int* __restrict__ itp, float* __restrict__ out) {
    __shared__ float xs[BCH][DIM];
    __shared__ float lrs[BCH][CB];
    __shared__ float sSs[CB];

    const int t  = threadIdx.x;
    const int c0 = blockIdx.x * CB;

    const float itf   = (float)(*itp);
    const float decay = 1.0f - itf / NITER_F;
    const float alpha = ALPHA_F * decay;
    const float sig   = SIGMA_F * decay;
    const float inv_s2 = 1.0f / (sig * sig);

    float4 acc[CB];
    #pragma unroll
    for (int c = 0; c < CB; c++) acc[c] = make_float4(0.f, 0.f, 0.f, 0.f);
    float sreg = 0.f;

    int ci = 0, cj = 0;
    if (t < BCH * CB) {
        int c = c0 + (t & 15);
        ci = c >> 7;
        cj = c & 127;
    }

    for (int b0 = 0; b0 < BS; b0 += BCH) {
        // stage 8 x-rows (coalesced float4)
        #pragma unroll
        for (int j = 0; j < 8; j++) {
            int idx = t + j * UPD_THREADS;        // 0..1535
            int row = idx / (DIM / 4);
            int col = idx % (DIM / 4);
            *(float4*)&xs[row][col * 4] =
                *(const float4*)&X[(size_t)(b0 + row) * DIM + col * 4];
        }
        // lr tile: 8 b x 16 c
        if (t < BCH * CB) {
            int b   = t >> 4;
            int bmu = g_bmu[b0 + b];
            float dx = (float)(ci - (bmu >> 7));
            float dy = (float)(cj - (bmu & 127));
            lrs[b][t & 15] = alpha * __expf(-(dx * dx + dy * dy) * inv_s2);
        }
        __syncthreads();

        if (t < CB) {
            #pragma unroll
            for (int b = 0; b < BCH; b++) sreg += lrs[b][t];
        }

        #pragma unroll
        for (int b = 0; b < BCH; b++) {
            float4 xv = *(const float4*)&xs[b][t * 4];
            #pragma unroll
            for (int c = 0; c < CB; c++) {
                float f = lrs[b][c];
                acc[c].x = fmaf(f, xv.x, acc[c].x);
                acc[c].y = fmaf(f, xv.y, acc[c].y);
                acc[c].z = fmaf(f, xv.z, acc[c].z);
                acc[c].w = fmaf(f, xv.w, acc[c].w);
            }
        }
        __syncthreads();
    }

    if (t < CB) sSs[t] = sreg;
    __syncthreads();

    #pragma unroll
    for (int c = 0; c < CB; c++) {
        float S = sSs[c];
        float4 w4 = *(const float4*)&W[(size_t)(c0 + c) * DIM + t * 4];
        float4 o;
        o.x = fmaf(w4.x, 1.f - S, acc[c].x);
        o.y = fmaf(w4.y, 1.f - S, acc[c].y);
        o.z = fmaf(w4.z, 1.f - S, acc[c].z);
        o.w = fmaf(w4.w, 1.f - S, acc[c].w);
        *(float4*)&out[(size_t)(c0 + c) * DIM + t * 4] = o;
    }
}

// ---------------------------------------------------------------------------
extern "C" void kernel_launch(void* const* d_in, const int* in_sizes, int n_in,
                              void* d_out, int out_size) {
    const float* X  = (const float*)d_in[0];   // embedded [4096, 768]
    const float* W  = (const float*)d_in[1];   // weights  [16384, 768]
    const int*   it = (const int*)d_in[2];     // scalar it
    float* out = (float*)d_out;                // [16384, 768]

    zero_keys_kernel<<<(BS + 255) / 256, 256>>>();
    wn_kernel<<<COMPS / 8, 256>>>(W);
    dim3 grid_bmu(COMPS / 64, BS / 64);
    bmu_kernel<<<grid_bmu, 256>>>(X, W);
    decode_kernel<<<(BS + 255) / 256, 256>>>();
    update_kernel<<<COMPS / CB, UPD_THREADS>>>(X, W, it, out);
}

// round 3
// speedup vs baseline: 1.2259x; 1.2259x over previous
#include <cuda_runtime.h>
#include <cuda_bf16.h>
#include <cstdint>

// Problem constants (fixed shapes)
#define SOM_M   128
#define SOM_N   128
#define COMPS   16384     // SOM_M * SOM_N
#define BS      4096
#define DIM     768
#define NITER_F 1000.0f
#define ALPHA_F 0.3f
#define SIGMA_F 64.0f     // max(M,N)/2

typedef unsigned long long u64;

// Device scratch (no allocations allowed in kernel_launch)
__device__ float g_wn[COMPS];
__device__ u64   g_key[BS];
__device__ int   g_bmu[BS];

// ---------------------------------------------------------------------------
// packed fp32x2 helpers (Blackwell FFMA2 — PTX-only)
__device__ __forceinline__ u64 fma2(u64 a, u64 b, u64 c) {
    u64 d;
    asm("fma.rn.f32x2 %0, %1, %2, %3;" : "=l"(d) : "l"(a), "l"(b), "l"(c));
    return d;
}
__device__ __forceinline__ u64 dup2(float x) {
    u64 d;
    unsigned u = __float_as_uint(x);
    asm("mov.b64 %0, {%1, %1};" : "=l"(d) : "r"(u));
    return d;
}
__device__ __forceinline__ float lo2(u64 v) { return __uint_as_float((unsigned)v); }
__device__ __forceinline__ float hi2(u64 v) { return __uint_as_float((unsigned)(v >> 32)); }

// monotone ordered encoding of float for integer max-compare
__device__ __forceinline__ unsigned ordf(float f) {
    unsigned u = __float_as_uint(f);
    return (u & 0x80000000u) ? ~u : (u | 0x80000000u);
}

// ---------------------------------------------------------------------------
// K0a: zero the argmax keys
__global__ void zero_keys_kernel() {
    int t = blockIdx.x * blockDim.x + threadIdx.x;
    if (t < BS) g_key[t] = 0ull;
}

// K0b: wn[c] = ||w_c||^2  (one warp per row)
__global__ void wn_kernel(const float* __restrict__ W) {
    int warp = threadIdx.x >> 5;
    int lane = threadIdx.x & 31;
    int c = blockIdx.x * 8 + warp;
    if (c >= COMPS) return;
    const float* row = &W[(size_t)c * DIM];
    float s = 0.f;
    #pragma unroll 6
    for (int i = lane; i < DIM; i += 32) {
        float v = row[i];
        s = fmaf(v, v, s);
    }
    #pragma unroll
    for (int o = 16; o > 0; o >>= 1) s += __shfl_xor_sync(0xFFFFFFFFu, s, o);
    if (lane == 0) g_wn[c] = s;
}

// ---------------------------------------------------------------------------
// K1: BMU search. CTA tile 64b x 128c, thread tile 4b x 8c, f32x2 packed
// along k. score[b,c] = x_b . w_c - 0.5*wn[c]; argmax epilogue.
#define BT  64
#define CT  128
#define KC  32
#define SST 34     // smem row stride in floats (conflict-free for LDS.64)

__global__ __launch_bounds__(256) void bmu_kernel(const float* __restrict__ X,
                                                  const float* __restrict__ W) {
    __shared__ float xs[BT * SST];
    __shared__ float ws[CT * SST];
    __shared__ u64 red[BT][16];

    const int t  = threadIdx.x;
    const int c0 = blockIdx.x * CT;
    const int b0 = blockIdx.y * BT;
    const int tby = t >> 4;    // 0..15 -> b rows tby + 16*i
    const int tcx = t & 15;    // 0..15 -> c cols tcx + 16*j

    u64 acc[4][8];
    #pragma unroll
    for (int i = 0; i < 4; i++)
        #pragma unroll
        for (int j = 0; j < 8; j++) acc[i][j] = 0ull;

    for (int k0 = 0; k0 < DIM; k0 += KC) {
        // stage as float2 (8B stores keep SST=34 alignment-legal)
        float2 xr[4], wr[8];
        #pragma unroll
        for (int r = 0; r < 4; r++) {
            int idx = t + 256 * r;
            int row = idx >> 4, cc = idx & 15;
            xr[r] = *(const float2*)&X[(size_t)(b0 + row) * DIM + k0 + 2 * cc];
        }
        #pragma unroll
        for (int r = 0; r < 8; r++) {
            int idx = t + 256 * r;
            int row = idx >> 4, cc = idx & 15;
            wr[r] = *(const float2*)&W[(size_t)(c0 + row) * DIM + k0 + 2 * cc];
        }
        __syncthreads();
        #pragma unroll
        for (int r = 0; r < 4; r++) {
            int idx = t + 256 * r;
            int row = idx >> 4, cc = idx & 15;
            *(float2*)&xs[row * SST + 2 * cc] = xr[r];
        }
        #pragma unroll
        for (int r = 0; r < 8; r++) {
            int idx = t + 256 * r;
            int row = idx >> 4, cc = idx & 15;
            *(float2*)&ws[row * SST + 2 * cc] = wr[r];
        }
        __syncthreads();

        #pragma unroll
        for (int kp = 0; kp < KC / 2; kp++) {
            u64 a2[4], b2[8];
            #pragma unroll
            for (int i = 0; i < 4; i++)
                a2[i] = *(const u64*)&xs[(tby + 16 * i) * SST + 2 * kp];
            #pragma unroll
            for (int j = 0; j < 8; j++)
                b2[j] = *(const u64*)&ws[(tcx + 16 * j) * SST + 2 * kp];
            #pragma unroll
            for (int i = 0; i < 4; i++)
                #pragma unroll
                for (int j = 0; j < 8; j++)
                    acc[i][j] = fma2(a2[j >= 0 ? i : i], b2[j], acc[i][j]);
        }
    }

    // epilogue: reduce k-pair lanes, argmax over this thread's 8 c per b row
    float wnj[8];
    #pragma unroll
    for (int j = 0; j < 8; j++) wnj[j] = g_wn[c0 + tcx + 16 * j];

    #pragma unroll
    for (int i = 0; i < 4; i++) {
        u64 best = 0ull;
        #pragma unroll
        for (int j = 0; j < 8; j++) {
            float score = lo2(acc[i][j]) + hi2(acc[i][j]) - 0.5f * wnj[j];
            unsigned cidx = (unsigned)(c0 + tcx + 16 * j);
            u64 key = ((u64)ordf(score) << 32) | (0xFFFFFFFFu - cidx);
            if (key > best) best = key;
        }
        red[tby + 16 * i][tcx] = best;
    }
    __syncthreads();
    if (t < BT) {
        u64 m = red[t][0];
        #pragma unroll
        for (int j = 1; j < 16; j++) {
            u64 v = red[t][j];
            if (v > m) m = v;
        }
        atomicMax(&g_key[b0 + t], m);
    }
}

// decode packed keys -> bmu indices
__global__ void decode_kernel() {
    int t = blockIdx.x * blockDim.x + threadIdx.x;
    if (t < BS)
        g_bmu[t] = (int)(0xFFFFFFFFu - (unsigned)(g_key[t] & 0xFFFFFFFFull));
}

// ---------------------------------------------------------------------------
// K2: update. One CTA owns 16 c-rows x full 768 d. f32x2 packed along c:
// lr pairs (c,c+1) come contiguous from SMEM (no packing); x is dup-packed
// once per (b,d) and reused across all 8 c-pairs.
#define CB  16
#define BCH 8
#define UPD_THREADS 192   // 192*4 = 768 d columns

__global__ __launch_bounds__(UPD_THREADS) void update_kernel(
    const float* __restrict__ X, const float* __restrict__ W,
    const int* __restrict__ itp, float* __restrict__ out) {
    __shared__ float xs[BCH][DIM];
    __shared__ float lrs[BCH][CB];
    __shared__ float sSs[CB];

    const int t  = threadIdx.x;
    const int c0 = blockIdx.x * CB;

    const float itf   = (float)(*itp);
    const float decay = 1.0f - itf / NITER_F;
    const float alpha = ALPHA_F * decay;
    const float sig   = SIGMA_F * decay;
    const float inv_s2 = 1.0f / (sig * sig);

    u64 acc[CB / 2][4];   // lanes: lo = c even, hi = c odd
    #pragma unroll
    for (int p = 0; p < CB / 2; p++)
        #pragma unroll
        for (int j = 0; j < 4; j++) acc[p][j] = 0ull;
    float sreg = 0.f;

    int ci = 0, cj = 0;
    if (t < BCH * CB) {
        int c = c0 + (t & 15);
        ci = c >> 7;
        cj = c & 127;
    }

    for (int b0 = 0; b0 < BS; b0 += BCH) {
        // stage 8 x-rows (coalesced float4)
        #pragma unroll
        for (int j = 0; j < BCH; j++)
            *(float4*)&xs[j][t * 4] =
                *(const float4*)&X[(size_t)(b0 + j) * DIM + t * 4];
        // lr tile: 8 b x 16 c
        if (t < BCH * CB) {
            int b   = t >> 4;
            int bmu = g_bmu[b0 + b];
            float dx = (float)(ci - (bmu >> 7));
            float dy = (float)(cj - (bmu & 127));
            lrs[b][t & 15] = alpha * __expf(-(dx * dx + dy * dy) * inv_s2);
        }
        __syncthreads();

        if (t < CB) {
            #pragma unroll
            for (int b = 0; b < BCH; b++) sreg += lrs[b][t];
        }

        #pragma unroll
        for (int b = 0; b < BCH; b++) {
            u64 lr2[CB / 2];
            const u64* lp = (const u64*)&lrs[b][0];
            #pragma unroll
            for (int p = 0; p < CB / 2; p++) lr2[p] = lp[p];   // broadcast LDS.64

            float4 xv = *(const float4*)&xs[b][t * 4];
            u64 xd0 = dup2(xv.x), xd1 = dup2(xv.y), xd2 = dup2(xv.z), xd3 = dup2(xv.w);
            #pragma unroll
            for (int p = 0; p < CB / 2; p++) {
                acc[p][0] = fma2(lr2[p], xd0, acc[p][0]);
                acc[p][1] = fma2(lr2[p], xd1, acc[p][1]);
                acc[p][2] = fma2(lr2[p], xd2, acc[p][2]);
                acc[p][3] = fma2(lr2[p], xd3, acc[p][3]);
            }
        }
        __syncthreads();
    }

    if (t < CB) sSs[t] = sreg;
    __syncthreads();

    #pragma unroll
    for (int c = 0; c < CB; c++) {
        float S = sSs[c];
        int p = c >> 1;
        bool hi = c & 1;
        float a0 = hi ? hi2(acc[p][0]) : lo2(acc[p][0]);
        float a1 = hi ? hi2(acc[p][1]) : lo2(acc[p][1]);
        float a2v = hi ? hi2(acc[p][2]) : lo2(acc[p][2]);
        float a3 = hi ? hi2(acc[p][3]) : lo2(acc[p][3]);
        float4 w4 = *(const float4*)&W[(size_t)(c0 + c) * DIM + t * 4];
        float4 o;
        o.x = fmaf(w4.x, 1.f - S, a0);
        o.y = fmaf(w4.y, 1.f - S, a1);
        o.z = fmaf(w4.z, 1.f - S, a2v);
        o.w = fmaf(w4.w, 1.f - S, a3);
        *(float4*)&out[(size_t)(c0 + c) * DIM + t * 4] = o;
    }
}

// ---------------------------------------------------------------------------
extern "C" void kernel_launch(void* const* d_in, const int* in_sizes, int n_in,
                              void* d_out, int out_size) {
    const float* X  = (const float*)d_in[0];   // embedded [4096, 768]
    const float* W  = (const float*)d_in[1];   // weights  [16384, 768]
    const int*   it = (const int*)d_in[2];     // scalar it
    float* out = (float*)d_out;                // [16384, 768]

    zero_keys_kernel<<<(BS + 255) / 256, 256>>>();
    wn_kernel<<<COMPS / 8, 256>>>(W);
    dim3 grid_bmu(COMPS / CT, BS / BT);
    bmu_kernel<<<grid_bmu, 256>>>(X, W);
    decode_kernel<<<(BS + 255) / 256, 256>>>();
    update_kernel<<<COMPS / CB, UPD_THREADS>>>(X, W, it, out);
}

// round 9
// speedup vs baseline: 1.7406x; 1.4198x over previous
#include <cuda_runtime.h>
#include <cuda_bf16.h>
#include <cstdint>

// Problem constants (fixed shapes)
#define SOM_M   128
#define SOM_N   128
#define COMPS   16384     // SOM_M * SOM_N
#define BS      4096
#define DIM     768
#define NITER_F 1000.0f
#define ALPHA_F 0.3f
#define SIGMA_F 64.0f     // max(M,N)/2

typedef unsigned long long u64;

// tcgen05 is an arch-specific ('a') feature: only compile it in the sm_103a
// (or sm_100a) pass. The plain compute_103 pass gets a scalar fallback body
// for the SAME kernel symbol, so whichever cubin the runtime selects is correct.
#if defined(__CUDA_ARCH_FEAT_SM103_ALL) || defined(__CUDA_ARCH_FEAT_SM100_ALL)
#define HAS_TC 1
#else
#define HAS_TC 0
#endif

// Device scratch (no allocations allowed in kernel_launch)
__device__ float g_wn[COMPS];
__device__ u64   g_key[BS];
__device__ int   g_bmu[BS];

// ---------------------------------------------------------------------------
// PTX helpers (arch-neutral)
__device__ __forceinline__ uint32_t smem_u32(const void* p) {
    uint32_t a;
    asm("{ .reg .u64 t; cvta.to.shared.u64 t, %1; cvt.u32.u64 %0, t; }"
        : "=r"(a) : "l"(p));
    return a;
}
__device__ __forceinline__ uint32_t elect_one_pred() {
    uint32_t p;
    asm volatile("{ .reg .pred p; elect.sync _|p, 0xFFFFFFFF; selp.b32 %0,1,0,p; }"
                 : "=r"(p));
    return p;
}
__device__ __forceinline__ u64 fma2(u64 a, u64 b, u64 c) {
    u64 d;
    asm("fma.rn.f32x2 %0, %1, %2, %3;" : "=l"(d) : "l"(a), "l"(b), "l"(c));
    return d;
}
__device__ __forceinline__ u64 dup2(float x) {
    u64 d;
    unsigned u = __float_as_uint(x);
    asm("mov.b64 %0, {%1, %1};" : "=l"(d) : "r"(u));
    return d;
}
__device__ __forceinline__ float lo2(u64 v) { return __uint_as_float((unsigned)v); }
__device__ __forceinline__ float hi2(u64 v) { return __uint_as_float((unsigned)(v >> 32)); }

__device__ __forceinline__ unsigned ordf(float f) {
    unsigned u = __float_as_uint(f);
    return (u & 0x80000000u) ? ~u : (u | 0x80000000u);
}

#define MBAR_INIT(a, c)   asm volatile("mbarrier.init.shared.b64 [%0], %1;" :: "r"(a), "r"(c) : "memory")
#define FENCE_ASYNC()     asm volatile("fence.proxy.async.shared::cta;" ::: "memory")

__device__ __forceinline__ void mbar_wait(uint32_t mb, uint32_t parity) {
    asm volatile(
        "{\n\t"
        ".reg .pred P1;\n\t"
        "WL_%=:\n\t"
        "mbarrier.try_wait.parity.acquire.cta.shared::cta.b64 P1, [%0], %1, 0x989680;\n\t"
        "@P1 bra.uni WD_%=;\n\t"
        "bra.uni WL_%=;\n\t"
        "WD_%=:\n\t"
        "}"
        :: "r"(mb), "r"(parity) : "memory");
}

#if HAS_TC
// --- tcgen05-only helpers ---
// SMEM descriptor: SW128, version=1 (Blackwell), SBO=64, LBO=1
static constexpr u64 DESC_BASE_SW128 =
    (u64(2) << 61) | (u64(1) << 46) | (u64(64) << 32) | (u64(1) << 16);
__device__ __forceinline__ u64 make_desc(uint32_t addr) {
    return DESC_BASE_SW128 | ((u64)(addr >> 4) & 0x3FFF);
}

__device__ __forceinline__ void mma_f16_ss(uint32_t d_tmem, u64 a_desc, u64 b_desc,
                                           uint32_t idesc, bool en_d) {
    uint32_t en = en_d ? 1u : 0u;
    asm volatile(
        "{\n\t"
        ".reg .pred p;\n\t"
        "setp.ne.u32 p, %5, 0;\n\t"
        "tcgen05.mma.cta_group::1.kind::f16 [%0], %1, %2, %3, {%4,%4,%4,%4}, p;\n\t"
        "}"
        :: "r"(d_tmem), "l"(a_desc), "l"(b_desc), "r"(idesc), "r"(0u), "r"(en)
        : "memory");
}

#define TC_ALLOC(sa, n)   asm volatile("tcgen05.alloc.cta_group::1.sync.aligned.shared::cta.b32 [%0], %1;" :: "r"(sa), "r"(n) : "memory")
#define TC_DEALLOC(tm, n) asm volatile("tcgen05.dealloc.cta_group::1.sync.aligned.b32 %0, %1;" :: "r"(tm), "r"(n))
#define TC_RELINQ()       asm volatile("tcgen05.relinquish_alloc_permit.cta_group::1.sync.aligned;")
#define TC_COMMIT(mb)     asm volatile("tcgen05.commit.cta_group::1.mbarrier::arrive::one.shared::cluster.b64 [%0];" :: "r"(mb) : "memory")
#define TC_FENCE_AFTER()  asm volatile("tcgen05.fence::after_thread_sync;" ::: "memory")
#define TC_WAIT_LD()      asm volatile("tcgen05.wait::ld.sync.aligned;" ::: "memory")

#define LDTM_X32(r, ta) \
    asm volatile( \
        "tcgen05.ld.sync.aligned.32x32b.x32.b32 " \
        "{%0,%1,%2,%3,%4,%5,%6,%7,%8,%9,%10,%11,%12,%13,%14,%15," \
        "%16,%17,%18,%19,%20,%21,%22,%23,%24,%25,%26,%27,%28,%29,%30,%31}, [%32];" \
        : "=r"((r)[0]),"=r"((r)[1]),"=r"((r)[2]),"=r"((r)[3]), \
          "=r"((r)[4]),"=r"((r)[5]),"=r"((r)[6]),"=r"((r)[7]), \
          "=r"((r)[8]),"=r"((r)[9]),"=r"((r)[10]),"=r"((r)[11]), \
          "=r"((r)[12]),"=r"((r)[13]),"=r"((r)[14]),"=r"((r)[15]), \
          "=r"((r)[16]),"=r"((r)[17]),"=r"((r)[18]),"=r"((r)[19]), \
          "=r"((r)[20]),"=r"((r)[21]),"=r"((r)[22]),"=r"((r)[23]), \
          "=r"((r)[24]),"=r"((r)[25]),"=r"((r)[26]),"=r"((r)[27]), \
          "=r"((r)[28]),"=r"((r)[29]),"=r"((r)[30]),"=r"((r)[31]) \
        : "r"(ta))
#endif  // HAS_TC

// ---------------------------------------------------------------------------
// K0a: zero the argmax keys
__global__ void zero_keys_kernel() {
    int t = blockIdx.x * blockDim.x + threadIdx.x;
    if (t < BS) g_key[t] = 0ull;
}

// K0b: wn[c] = ||w_c||^2  (one warp per row)
__global__ void wn_kernel(const float* __restrict__ W) {
    int warp = threadIdx.x >> 5;
    int lane = threadIdx.x & 31;
    int c = blockIdx.x * 8 + warp;
    if (c >= COMPS) return;
    const float* row = &W[(size_t)c * DIM];
    float s = 0.f;
    #pragma unroll 6
    for (int i = lane; i < DIM; i += 32) {
        float v = row[i];
        s = fmaf(v, v, s);
    }
    #pragma unroll
    for (int o = 16; o > 0; o >>= 1) s += __shfl_xor_sync(0xFFFFFFFFu, s, o);
    if (lane == 0) g_wn[c] = s;
}

// ---------------------------------------------------------------------------
// K1: BMU. CTA tile 128 b x 256 c.
//   sm_103a cubin: tcgen05 bf16-split (Ah*Bh + Al*Bh + Ah*Bl), K chunked by 64.
//   sm_103 cubin : f32x2 scalar tile path (4 sub-passes of 64b x 128c).
// score[b,c] = x.w - 0.5*wn[c]; argmax epilogue.

#define KCH      64
#define NCHUNKS  (DIM / KCH)          // 12
// idesc: F32 out, BF16 a/b, M=128, N=128
#define BMU_IDESC ((1u<<4) | (1u<<7) | (1u<<10) | ((128u/8)<<17) | ((128u/16)<<24))

// dynamic smem offsets (bytes) — tiles 1024-aligned for SW128
#define SM_TMEMPTR 0
#define SM_MBAR    8
#define SM_A_HI    1024
#define SM_A_LO    (SM_A_HI + 16384)
#define SM_BH      (SM_A_LO + 16384)         // tile t: hi at SM_BH + t*32768, lo = hi+16384
#define SMEM_BMU   (SM_BH + 2 * 32768)       // 99328

__global__ __launch_bounds__(256) void bmu_mma_kernel(const float* __restrict__ X,
                                                      const float* __restrict__ W) {
    extern __shared__ char smem[];
    const int t    = threadIdx.x;
    const int c0 = blockIdx.x * 256;
    const int b0 = blockIdx.y * 128;

#if HAS_TC
    const uint32_t sb = smem_u32(smem);
    const int wid  = t >> 5;
    const int lane = t & 31;

    if (wid == 0) {
        TC_ALLOC(sb + SM_TMEMPTR, 256);
        TC_RELINQ();
    }
    if (t == 0) MBAR_INIT(sb + SM_MBAR, 1);
    __syncthreads();
    uint32_t tmem;
    asm volatile("ld.shared.b32 %0, [%1];" : "=r"(tmem) : "r"(sb + SM_TMEMPTR));

    for (int kc = 0; kc < NCHUNKS; kc++) {
        const int k0 = kc * KCH;

        // ---- stage A: 128 rows x 32 col-pairs, fp32->bf16 hi/lo packed u32 ----
        #pragma unroll 4
        for (int it = 0; it < 16; it++) {
            int e   = t + it * 256;
            int row = e >> 5, cp = e & 31;
            float2 v = *(const float2*)&X[(size_t)(b0 + row) * DIM + k0 + 2 * cp];
            __nv_bfloat16 h0 = __float2bfloat16(v.x);
            __nv_bfloat16 h1 = __float2bfloat16(v.y);
            __nv_bfloat16 l0 = __float2bfloat16(v.x - __bfloat162float(h0));
            __nv_bfloat16 l1 = __float2bfloat16(v.y - __bfloat162float(h1));
            uint32_t hp = ((uint32_t)__bfloat16_as_ushort(h1) << 16) |
                          __bfloat16_as_ushort(h0);
            uint32_t lp = ((uint32_t)__bfloat16_as_ushort(l1) << 16) |
                          __bfloat16_as_ushort(l0);
            int off = row * 128 + cp * 4;
            int sw  = off ^ ((off >> 3) & 0x70);
            *(uint32_t*)(smem + SM_A_HI + sw) = hp;
            *(uint32_t*)(smem + SM_A_LO + sw) = lp;
        }
        // ---- stage B: 2 tiles x 128 rows x 32 col-pairs ----
        #pragma unroll 4
        for (int it = 0; it < 32; it++) {
            int e    = t + it * 256;
            int tile = e >> 12;
            int row  = (e >> 5) & 127, cp = e & 31;
            float2 v = *(const float2*)&W[(size_t)(c0 + tile * 128 + row) * DIM + k0 + 2 * cp];
            __nv_bfloat16 h0 = __float2bfloat16(v.x);
            __nv_bfloat16 h1 = __float2bfloat16(v.y);
            __nv_bfloat16 l0 = __float2bfloat16(v.x - __bfloat162float(h0));
            __nv_bfloat16 l1 = __float2bfloat16(v.y - __bfloat162float(h1));
            uint32_t hp = ((uint32_t)__bfloat16_as_ushort(h1) << 16) |
                          __bfloat16_as_ushort(h0);
            uint32_t lp = ((uint32_t)__bfloat16_as_ushort(l1) << 16) |
                          __bfloat16_as_ushort(l0);
            int off  = row * 128 + cp * 4;
            int sw   = off ^ ((off >> 3) & 0x70);
            int base = SM_BH + tile * 32768;
            *(uint32_t*)(smem + base + sw)         = hp;
            *(uint32_t*)(smem + base + 16384 + sw) = lp;
        }
        FENCE_ASYNC();
        __syncthreads();

        // ---- issue MMAs (single elected thread) ----
        if (wid == 0 && elect_one_pred()) {
            u64 dah = make_desc(sb + SM_A_HI);
            u64 dal = make_desc(sb + SM_A_LO);
            #pragma unroll
            for (int ct = 0; ct < 2; ct++) {
                u64 dbh = make_desc(sb + SM_BH + ct * 32768);
                u64 dbl = make_desc(sb + SM_BH + ct * 32768 + 16384);
                uint32_t D = tmem + ct * 128;
                #pragma unroll
                for (int s = 0; s < 4; s++) {
                    mma_f16_ss(D, dah + 2 * s, dbh + 2 * s, BMU_IDESC,
                               !(kc == 0 && s == 0));
                    mma_f16_ss(D, dal + 2 * s, dbh + 2 * s, BMU_IDESC, true);
                    mma_f16_ss(D, dah + 2 * s, dbl + 2 * s, BMU_IDESC, true);
                }
            }
            TC_COMMIT(sb + SM_MBAR);
        }
        // all threads wait: MMA done before SMEM is restaged
        mbar_wait(sb + SM_MBAR, (uint32_t)(kc & 1));
    }

    TC_FENCE_AFTER();

    // ---- epilogue: warps 0-3 own TMEM lanes (b rows); argmax over 256 c ----
    if (wid < 4) {
        const int b = b0 + wid * 32 + lane;
        u64 best = 0ull;
        #pragma unroll
        for (int ct = 0; ct < 2; ct++) {
            #pragma unroll
            for (int ch = 0; ch < 4; ch++) {
                uint32_t r[32];
                LDTM_X32(r, tmem + ct * 128 + ch * 32);
                TC_WAIT_LD();
                int cbase = c0 + ct * 128 + ch * 32;
                #pragma unroll
                for (int j = 0; j < 32; j++) {
                    float score = __uint_as_float(r[j]) - 0.5f * g_wn[cbase + j];
                    u64 key = ((u64)ordf(score) << 32) |
                              (0xFFFFFFFFu - (unsigned)(cbase + j));
                    if (key > best) best = key;
                }
            }
        }
        atomicMax(&g_key[b], best);
    }

    __syncthreads();
    if (wid == 0) TC_DEALLOC(tmem, 256);

#else  // ---------------- scalar f32x2 fallback (plain sm_103 cubin) --------
    #define FB_SST 34
    float* xs = (float*)smem;                              // 64*34 floats
    float* ws = (float*)(smem + 64 * FB_SST * 4);          // 128*34 floats
    u64 (*red)[16] = (u64(*)[16])(smem + (64 + 128) * FB_SST * 4);

    const int tby = t >> 4;    // b rows tby + 16*i
    const int tcx = t & 15;    // c cols tcx + 16*j

    for (int pass = 0; pass < 4; pass++) {
        const int bo = b0 + (pass >> 1) * 64;
        const int co = c0 + (pass & 1) * 128;

        u64 acc[4][8];
        #pragma unroll
        for (int i = 0; i < 4; i++)
            #pragma unroll
            for (int j = 0; j < 8; j++) acc[i][j] = 0ull;

        for (int k0 = 0; k0 < DIM; k0 += 32) {
            float2 xr[4], wr[8];
            #pragma unroll
            for (int r = 0; r < 4; r++) {
                int idx = t + 256 * r;
                int row = idx >> 4, cc = idx & 15;
                xr[r] = *(const float2*)&X[(size_t)(bo + row) * DIM + k0 + 2 * cc];
            }
            #pragma unroll
            for (int r = 0; r < 8; r++) {
                int idx = t + 256 * r;
                int row = idx >> 4, cc = idx & 15;
                wr[r] = *(const float2*)&W[(size_t)(co + row) * DIM + k0 + 2 * cc];
            }
            __syncthreads();
            #pragma unroll
            for (int r = 0; r < 4; r++) {
                int idx = t + 256 * r;
                int row = idx >> 4, cc = idx & 15;
                *(float2*)&xs[row * FB_SST + 2 * cc] = xr[r];
            }
            #pragma unroll
            for (int r = 0; r < 8; r++) {
                int idx = t + 256 * r;
                int row = idx >> 4, cc = idx & 15;
                *(float2*)&ws[row * FB_SST + 2 * cc] = wr[r];
            }
            __syncthreads();

            #pragma unroll
            for (int kp = 0; kp < 16; kp++) {
                u64 a2[4], b2[8];
                #pragma unroll
                for (int i = 0; i < 4; i++)
                    a2[i] = *(const u64*)&xs[(tby + 16 * i) * FB_SST + 2 * kp];
                #pragma unroll
                for (int j = 0; j < 8; j++)
                    b2[j] = *(const u64*)&ws[(tcx + 16 * j) * FB_SST + 2 * kp];
                #pragma unroll
                for (int i = 0; i < 4; i++)
                    #pragma unroll
                    for (int j = 0; j < 8; j++)
                        acc[i][j] = fma2(a2[i], b2[j], acc[i][j]);
            }
        }

        float wnj[8];
        #pragma unroll
        for (int j = 0; j < 8; j++) wnj[j] = g_wn[co + tcx + 16 * j];

        #pragma unroll
        for (int i = 0; i < 4; i++) {
            u64 best = 0ull;
            #pragma unroll
            for (int j = 0; j < 8; j++) {
                float score = lo2(acc[i][j]) + hi2(acc[i][j]) - 0.5f * wnj[j];
                unsigned cidx = (unsigned)(co + tcx + 16 * j);
                u64 key = ((u64)ordf(score) << 32) | (0xFFFFFFFFu - cidx);
                if (key > best) best = key;
            }
            red[tby + 16 * i][tcx] = best;
        }
        __syncthreads();
        if (t < 64) {
            u64 m = red[t][0];
            #pragma unroll
            for (int j = 1; j < 16; j++) {
                u64 v = red[t][j];
                if (v > m) m = v;
            }
            atomicMax(&g_key[bo + t], m);
        }
        __syncthreads();
    }
#endif
}

// decode packed keys -> bmu indices
__global__ void decode_kernel() {
    int t = blockIdx.x * blockDim.x + threadIdx.x;
    if (t < BS)
        g_bmu[t] = (int)(0xFFFFFFFFu - (unsigned)(g_key[t] & 0xFFFFFFFFull));
}

// ---------------------------------------------------------------------------
// K2: update (f32x2). One CTA = 16 c-rows x 768 d.
#define CB  16
#define BCH 8
#define UPD_THREADS 192   // 192*4 = 768 d columns

__global__ __launch_bounds__(UPD_THREADS) void update_kernel(
    const float* __restrict__ X, const float* __restrict__ W,
    const int* __restrict__ itp, float* __restrict__ out) {
    __shared__ float xs[BCH][DIM];
    __shared__ float lrs[BCH][CB];
    __shared__ float sSs[CB];

    const int t  = threadIdx.x;
    const int c0 = blockIdx.x * CB;

    const float itf   = (float)(*itp);
    const float decay = 1.0f - itf / NITER_F;
    const float alpha = ALPHA_F * decay;
    const float sig   = SIGMA_F * decay;
    const float inv_s2 = 1.0f / (sig * sig);

    u64 acc[CB / 2][4];   // lanes: lo = c even, hi = c odd
    #pragma unroll
    for (int p = 0; p < CB / 2; p++)
        #pragma unroll
        for (int j = 0; j < 4; j++) acc[p][j] = 0ull;
    float sreg = 0.f;

    int ci = 0, cj = 0;
    if (t < BCH * CB) {
        int c = c0 + (t & 15);
        ci = c >> 7;
        cj = c & 127;
    }

    for (int b0 = 0; b0 < BS; b0 += BCH) {
        #pragma unroll
        for (int j = 0; j < BCH; j++)
            *(float4*)&xs[j][t * 4] =
                *(const float4*)&X[(size_t)(b0 + j) * DIM + t * 4];
        if (t < BCH * CB) {
            int b   = t >> 4;
            int bmu = g_bmu[b0 + b];
            float dx = (float)(ci - (bmu >> 7));
            float dy = (float)(cj - (bmu & 127));
            lrs[b][t & 15] = alpha * __expf(-(dx * dx + dy * dy) * inv_s2);
        }
        __syncthreads();

        if (t < CB) {
            #pragma unroll
            for (int b = 0; b < BCH; b++) sreg += lrs[b][t];
        }

        #pragma unroll
        for (int b = 0; b < BCH; b++) {
            u64 lr2[CB / 2];
            const u64* lp = (const u64*)&lrs[b][0];
            #pragma unroll
            for (int p = 0; p < CB / 2; p++) lr2[p] = lp[p];

            float4 xv = *(const float4*)&xs[b][t * 4];
            u64 xd0 = dup2(xv.x), xd1 = dup2(xv.y), xd2 = dup2(xv.z), xd3 = dup2(xv.w);
            #pragma unroll
            for (int p = 0; p < CB / 2; p++) {
                acc[p][0] = fma2(lr2[p], xd0, acc[p][0]);
                acc[p][1] = fma2(lr2[p], xd1, acc[p][1]);
                acc[p][2] = fma2(lr2[p], xd2, acc[p][2]);
                acc[p][3] = fma2(lr2[p], xd3, acc[p][3]);
            }
        }
        __syncthreads();
    }

    if (t < CB) sSs[t] = sreg;
    __syncthreads();

    #pragma unroll
    for (int c = 0; c < CB; c++) {
        float S = sSs[c];
        int p = c >> 1;
        bool hi = c & 1;
        float a0 = hi ? hi2(acc[p][0]) : lo2(acc[p][0]);
        float a1 = hi ? hi2(acc[p][1]) : lo2(acc[p][1]);
        float a2v = hi ? hi2(acc[p][2]) : lo2(acc[p][2]);
        float a3 = hi ? hi2(acc[p][3]) : lo2(acc[p][3]);
        float4 w4 = *(const float4*)&W[(size_t)(c0 + c) * DIM + t * 4];
        float4 o;
        o.x = fmaf(w4.x, 1.f - S, a0);
        o.y = fmaf(w4.y, 1.f - S, a1);
        o.z = fmaf(w4.z, 1.f - S, a2v);
        o.w = fmaf(w4.w, 1.f - S, a3);
        *(float4*)&out[(size_t)(c0 + c) * DIM + t * 4] = o;
    }
}

// ---------------------------------------------------------------------------
extern "C" void kernel_launch(void* const* d_in, const int* in_sizes, int n_in,
                              void* d_out, int out_size) {
    const float* X  = (const float*)d_in[0];   // embedded [4096, 768]
    const float* W  = (const float*)d_in[1];   // weights  [16384, 768]
    const int*   it = (const int*)d_in[2];     // scalar it
    float* out = (float*)d_out;                // [16384, 768]

    cudaFuncSetAttribute(bmu_mma_kernel,
                         cudaFuncAttributeMaxDynamicSharedMemorySize, SMEM_BMU);

    zero_keys_kernel<<<(BS + 255) / 256, 256>>>();
    wn_kernel<<<COMPS / 8, 256>>>(W);
    dim3 grid_bmu(COMPS / 256, BS / 128);
    bmu_mma_kernel<<<grid_bmu, 256, SMEM_BMU>>>(X, W);
    decode_kernel<<<(BS + 255) / 256, 256>>>();
    update_kernel<<<COMPS / CB, UPD_THREADS>>>(X, W, it, out);
}

// round 10
// speedup vs baseline: 5.6230x; 3.2305x over previous
#include <cuda_runtime.h>
#include <cuda_bf16.h>
#include <cstdint>
#include <cstdlib>

// Problem constants (fixed shapes)
#define SOM_M   128
#define SOM_N   128
#define COMPS   16384     // SOM_M * SOM_N
#define BS      4096
#define DIM     768
#define NITER_F 1000.0f
#define ALPHA_F 0.3f
#define SIGMA_F 64.0f     // max(M,N)/2

typedef unsigned long long u64;

// tcgen05 is an arch-specific ('a') feature: only compile it in the sm_103a
// (or sm_100a) pass. The plain compute_103 pass gets scalar fallback bodies
// for the SAME kernel symbols.
#if defined(__CUDA_ARCH_FEAT_SM103_ALL) || defined(__CUDA_ARCH_FEAT_SM100_ALL)
#define HAS_TC 1
#else
#define HAS_TC 0
#endif

// ---------------------------------------------------------------------------
// Device scratch (no allocations allowed in kernel_launch)
__device__ float g_wn[COMPS];
__device__ u64   g_key[BS];
__device__ int   g_bmu[BS];
__device__ int   g_hist[COMPS];     // BMU histogram over the 128x128 grid
__device__ float g_T[COMPS];        // intermediate of separable S-convolution
__device__ float g_S[COMPS];        // S[c] = sum_b lr[b,c]
// bf16 hi/lo splits (packed 8 bf16 = one uint4)
__device__ uint4 g_wh4[COMPS * DIM / 8];
__device__ uint4 g_wl4[COMPS * DIM / 8];
__device__ uint4 g_xh4[BS * DIM / 8];       // X, b-major (for BMU)
__device__ uint4 g_xl4[BS * DIM / 8];
__device__ uint4 g_xth4[DIM * BS / 8];      // X^T, d-major (for update)
__device__ uint4 g_xtl4[DIM * BS / 8];

// ---------------------------------------------------------------------------
// PTX helpers (arch-neutral)
__device__ __forceinline__ uint32_t smem_u32(const void* p) {
    uint32_t a;
    asm("{ .reg .u64 t; cvta.to.shared.u64 t, %1; cvt.u32.u64 %0, t; }"
        : "=r"(a) : "l"(p));
    return a;
}
__device__ __forceinline__ uint32_t elect_one_pred() {
    uint32_t p;
    asm volatile("{ .reg .pred p; elect.sync _|p, 0xFFFFFFFF; selp.b32 %0,1,0,p; }"
                 : "=r"(p));
    return p;
}
__device__ __forceinline__ u64 fma2(u64 a, u64 b, u64 c) {
    u64 d;
    asm("fma.rn.f32x2 %0, %1, %2, %3;" : "=l"(d) : "l"(a), "l"(b), "l"(c));
    return d;
}
__device__ __forceinline__ float lo2(u64 v) { return __uint_as_float((unsigned)v); }
__device__ __forceinline__ float hi2(u64 v) { return __uint_as_float((unsigned)(v >> 32)); }

__device__ __forceinline__ unsigned ordf(float f) {
    unsigned u = __float_as_uint(f);
    return (u & 0x80000000u) ? ~u : (u | 0x80000000u);
}

__device__ __forceinline__ uint32_t pack_bf16(float a, float b) {
    return ((uint32_t)__bfloat16_as_ushort(__float2bfloat16(b)) << 16) |
           __bfloat16_as_ushort(__float2bfloat16(a));
}
// split 8 consecutive floats into packed bf16 hi/lo uint4s (identical math to
// the staging conversion used in prior passing rounds)
__device__ __forceinline__ void split8(const float* v, uint4& hi, uint4& lo) {
    uint32_t h[4], l[4];
    #pragma unroll
    for (int k = 0; k < 4; k++) {
        float a = v[2 * k], b = v[2 * k + 1];
        __nv_bfloat16 ha = __float2bfloat16(a), hb = __float2bfloat16(b);
        float la = a - __bfloat162float(ha);
        float lb = b - __bfloat162float(hb);
        h[k] = ((uint32_t)__bfloat16_as_ushort(hb) << 16) | __bfloat16_as_ushort(ha);
        l[k] = pack_bf16(la, lb);
    }
    hi = make_uint4(h[0], h[1], h[2], h[3]);
    lo = make_uint4(l[0], l[1], l[2], l[3]);
}

#define MBAR_INIT(a, c)   asm volatile("mbarrier.init.shared.b64 [%0], %1;" :: "r"(a), "r"(c) : "memory")
#define FENCE_ASYNC()     asm volatile("fence.proxy.async.shared::cta;" ::: "memory")

__device__ __forceinline__ void mbar_wait(uint32_t mb, uint32_t parity) {
    asm volatile(
        "{\n\t"
        ".reg .pred P1;\n\t"
        "WL_%=:\n\t"
        "mbarrier.try_wait.parity.acquire.cta.shared::cta.b64 P1, [%0], %1, 0x989680;\n\t"
        "@P1 bra.uni WD_%=;\n\t"
        "bra.uni WL_%=;\n\t"
        "WD_%=:\n\t"
        "}"
        :: "r"(mb), "r"(parity) : "memory");
}

#if HAS_TC
// --- tcgen05-only helpers ---
static constexpr u64 DESC_BASE_SW128 =
    (u64(2) << 61) | (u64(1) << 46) | (u64(64) << 32) | (u64(1) << 16);
__device__ __forceinline__ u64 make_desc(uint32_t addr) {
    return DESC_BASE_SW128 | ((u64)(addr >> 4) & 0x3FFF);
}

__device__ __forceinline__ void mma_f16_ss(uint32_t d_tmem, u64 a_desc, u64 b_desc,
                                           uint32_t idesc, bool en_d) {
    uint32_t en = en_d ? 1u : 0u;
    asm volatile(
        "{\n\t"
        ".reg .pred p;\n\t"
        "setp.ne.u32 p, %5, 0;\n\t"
        "tcgen05.mma.cta_group::1.kind::f16 [%0], %1, %2, %3, {%4,%4,%4,%4}, p;\n\t"
        "}"
        :: "r"(d_tmem), "l"(a_desc), "l"(b_desc), "r"(idesc), "r"(0u), "r"(en)
        : "memory");
}

#define TC_ALLOC(sa, n)   asm volatile("tcgen05.alloc.cta_group::1.sync.aligned.shared::cta.b32 [%0], %1;" :: "r"(sa), "r"(n) : "memory")
#define TC_DEALLOC(tm, n) asm volatile("tcgen05.dealloc.cta_group::1.sync.aligned.b32 %0, %1;" :: "r"(tm), "r"(n))
#define TC_RELINQ()       asm volatile("tcgen05.relinquish_alloc_permit.cta_group::1.sync.aligned;")
#define TC_COMMIT(mb)     asm volatile("tcgen05.commit.cta_group::1.mbarrier::arrive::one.shared::cluster.b64 [%0];" :: "r"(mb) : "memory")
#define TC_FENCE_AFTER()  asm volatile("tcgen05.fence::after_thread_sync;" ::: "memory")
#define TC_WAIT_LD()      asm volatile("tcgen05.wait::ld.sync.aligned;" ::: "memory")

#define LDTM_X32(r, ta) \
    asm volatile( \
        "tcgen05.ld.sync.aligned.32x32b.x32.b32 " \
        "{%0,%1,%2,%3,%4,%5,%6,%7,%8,%9,%10,%11,%12,%13,%14,%15," \
        "%16,%17,%18,%19,%20,%21,%22,%23,%24,%25,%26,%27,%28,%29,%30,%31}, [%32];" \
        : "=r"((r)[0]),"=r"((r)[1]),"=r"((r)[2]),"=r"((r)[3]), \
          "=r"((r)[4]),"=r"((r)[5]),"=r"((r)[6]),"=r"((r)[7]), \
          "=r"((r)[8]),"=r"((r)[9]),"=r"((r)[10]),"=r"((r)[11]), \
          "=r"((r)[12]),"=r"((r)[13]),"=r"((r)[14]),"=r"((r)[15]), \
          "=r"((r)[16]),"=r"((r)[17]),"=r"((r)[18]),"=r"((r)[19]), \
          "=r"((r)[20]),"=r"((r)[21]),"=r"((r)[22]),"=r"((r)[23]), \
          "=r"((r)[24]),"=r"((r)[25]),"=r"((r)[26]),"=r"((r)[27]), \
          "=r"((r)[28]),"=r"((r)[29]),"=r"((r)[30]),"=r"((r)[31]) \
        : "r"(ta))
#endif  // HAS_TC

// ---------------------------------------------------------------------------
// K0: zero keys + histogram
__global__ void prep_kernel() {
    int t = blockIdx.x * blockDim.x + threadIdx.x;
    if (t < COMPS) g_hist[t] = 0;
    if (t < BS)    g_key[t]  = 0ull;
}

// K0b: wn[c] = ||w_c||^2  (one warp per row)
__global__ void wn_kernel(const float* __restrict__ W) {
    int warp = threadIdx.x >> 5;
    int lane = threadIdx.x & 31;
    int c = blockIdx.x * 8 + warp;
    if (c >= COMPS) return;
    const float* row = &W[(size_t)c * DIM];
    float s = 0.f;
    #pragma unroll 6
    for (int i = lane; i < DIM; i += 32) {
        float v = row[i];
        s = fmaf(v, v, s);
    }
    #pragma unroll
    for (int o = 16; o > 0; o >>= 1) s += __shfl_xor_sync(0xFFFFFFFFu, s, o);
    if (lane == 0) g_wn[c] = s;
}

// K0c: W fp32 -> bf16 hi/lo packed
__global__ void split_w_kernel(const float* __restrict__ W) {
    int idx = blockIdx.x * blockDim.x + threadIdx.x;    // one uint4 (8 elems)
    if (idx >= COMPS * DIM / 8) return;
    float v[8];
    const float4* p = (const float4*)W + (size_t)idx * 2;
    float4 a = p[0], b = p[1];
    v[0]=a.x; v[1]=a.y; v[2]=a.z; v[3]=a.w;
    v[4]=b.x; v[5]=b.y; v[6]=b.z; v[7]=b.w;
    uint4 hi, lo;
    split8(v, hi, lo);
    g_wh4[idx] = hi;
    g_wl4[idx] = lo;
}

// K0d: X -> bf16 hi/lo (b-major) AND X^T -> bf16 hi/lo (d-major)
__global__ void split_x_t_kernel(const float* __restrict__ X) {
    __shared__ float tile[32][33];
    const int t  = threadIdx.x;
    const int tx = t & 31, ty = t >> 5;       // 8 rows per pass
    const int b0 = blockIdx.x * 32;
    const int d0 = blockIdx.y * 32;

    #pragma unroll
    for (int i = 0; i < 4; i++)
        tile[ty + 8 * i][tx] = X[(size_t)(b0 + ty + 8 * i) * DIM + d0 + tx];
    __syncthreads();

    if (t < 128) {
        // non-transposed split
        int brow = t >> 2, blk = t & 3;
        float v[8];
        #pragma unroll
        for (int k = 0; k < 8; k++) v[k] = tile[brow][blk * 8 + k];
        uint4 hi, lo;
        split8(v, hi, lo);
        size_t idx = (size_t)(b0 + brow) * (DIM / 8) + d0 / 8 + blk;
        g_xh4[idx] = hi;
        g_xl4[idx] = lo;
    } else {
        // transposed split
        int t2 = t - 128;
        int drow = t2 >> 2, blkb = t2 & 3;
        float v[8];
        #pragma unroll
        for (int k = 0; k < 8; k++) v[k] = tile[blkb * 8 + k][drow];
        uint4 hi, lo;
        split8(v, hi, lo);
        size_t idx = (size_t)(d0 + drow) * (BS / 8) + b0 / 8 + blkb;
        g_xth4[idx] = hi;
        g_xtl4[idx] = lo;
    }
}

// ---------------------------------------------------------------------------
// K1: BMU. CTA tile 128 b x 256 c; tcgen05 bf16-split from pre-split tiles.
#define KCH      64
#define NCHUNKS  (DIM / KCH)          // 12
#define BMU_IDESC ((1u<<4) | (1u<<7) | (1u<<10) | ((128u/8)<<17) | ((128u/16)<<24))

#define SM_TMEMPTR 0
#define SM_MBAR    8
#define SM_A_HI    1024
#define SM_A_LO    (SM_A_HI + 16384)
#define SM_BH      (SM_A_LO + 16384)
#define SMEM_BMU   (SM_BH + 2 * 32768)       // 99328

__global__ __launch_bounds__(256) void bmu_mma_kernel(const float* __restrict__ X,
                                                      const float* __restrict__ W) {
    extern __shared__ char smem[];
    const int t  = threadIdx.x;
    const int c0 = blockIdx.x * 256;
    const int b0 = blockIdx.y * 128;

#if HAS_TC
    const uint32_t sb = smem_u32(smem);
    const int wid  = t >> 5;
    const int lane = t & 31;

    if (wid == 0) {
        TC_ALLOC(sb + SM_TMEMPTR, 256);
        TC_RELINQ();
    }
    if (t == 0) MBAR_INIT(sb + SM_MBAR, 1);
    __syncthreads();
    uint32_t tmem;
    asm volatile("ld.shared.b32 %0, [%1];" : "=r"(tmem) : "r"(sb + SM_TMEMPTR));

    for (int kc = 0; kc < NCHUNKS; kc++) {
        const int k8 = kc * (KCH / 8);       // uint4 column offset

        // ---- A (X): 128 rows x 8 blocks, hi+lo = 2048 uint4 copies ----
        #pragma unroll
        for (int it = 0; it < 8; it++) {
            int e = t + it * 256;
            int pol = e >> 10;
            int idx = e & 1023;
            int row = idx >> 3, blk = idx & 7;
            uint4 v = (pol ? g_xl4 : g_xh4)[(size_t)(b0 + row) * (DIM / 8) + k8 + blk];
            int off = row * 128 + blk * 16;
            int sw  = off ^ ((off >> 3) & 0x70);
            *(uint4*)(smem + (pol ? SM_A_LO : SM_A_HI) + sw) = v;
        }
        // ---- B (W): 2 tiles x 128 rows x 8 blocks, hi+lo = 4096 uint4 ----
        #pragma unroll
        for (int it = 0; it < 16; it++) {
            int e = t + it * 256;
            int tp = e >> 10;
            int tile = tp >> 1, pol = tp & 1;
            int idx = e & 1023;
            int row = idx >> 3, blk = idx & 7;
            uint4 v = (pol ? g_wl4 : g_wh4)[
                (size_t)(c0 + tile * 128 + row) * (DIM / 8) + k8 + blk];
            int off = row * 128 + blk * 16;
            int sw  = off ^ ((off >> 3) & 0x70);
            *(uint4*)(smem + SM_BH + tile * 32768 + pol * 16384 + sw) = v;
        }
        FENCE_ASYNC();
        __syncthreads();

        if (wid == 0 && elect_one_pred()) {
            u64 dah = make_desc(sb + SM_A_HI);
            u64 dal = make_desc(sb + SM_A_LO);
            #pragma unroll
            for (int ct = 0; ct < 2; ct++) {
                u64 dbh = make_desc(sb + SM_BH + ct * 32768);
                u64 dbl = make_desc(sb + SM_BH + ct * 32768 + 16384);
                uint32_t D = tmem + ct * 128;
                #pragma unroll
                for (int s = 0; s < 4; s++) {
                    mma_f16_ss(D, dah + 2 * s, dbh + 2 * s, BMU_IDESC,
                               !(kc == 0 && s == 0));
                    mma_f16_ss(D, dal + 2 * s, dbh + 2 * s, BMU_IDESC, true);
                    mma_f16_ss(D, dah + 2 * s, dbl + 2 * s, BMU_IDESC, true);
                }
            }
            TC_COMMIT(sb + SM_MBAR);
        }
        mbar_wait(sb + SM_MBAR, (uint32_t)(kc & 1));
    }

    TC_FENCE_AFTER();

    if (wid < 4) {
        const int b = b0 + wid * 32 + lane;
        u64 best = 0ull;
        #pragma unroll
        for (int ct = 0; ct < 2; ct++) {
            #pragma unroll
            for (int ch = 0; ch < 4; ch++) {
                uint32_t r[32];
                LDTM_X32(r, tmem + ct * 128 + ch * 32);
                TC_WAIT_LD();
                int cbase = c0 + ct * 128 + ch * 32;
                #pragma unroll
                for (int j = 0; j < 32; j++) {
                    float score = __uint_as_float(r[j]) - 0.5f * g_wn[cbase + j];
                    u64 key = ((u64)ordf(score) << 32) |
                              (0xFFFFFFFFu - (unsigned)(cbase + j));
                    if (key > best) best = key;
                }
            }
        }
        atomicMax(&g_key[b], best);
    }

    __syncthreads();
    if (wid == 0) TC_DEALLOC(tmem, 256);

#else  // ---------------- scalar f32x2 fallback (plain sm_103 cubin) --------
    #define FB_SST 34
    float* xs = (float*)smem;
    float* ws = (float*)(smem + 64 * FB_SST * 4);
    u64 (*red)[16] = (u64(*)[16])(smem + (64 + 128) * FB_SST * 4);

    const int tby = t >> 4;
    const int tcx = t & 15;

    for (int pass = 0; pass < 4; pass++) {
        const int bo = b0 + (pass >> 1) * 64;
        const int co = c0 + (pass & 1) * 128;

        u64 acc[4][8];
        #pragma unroll
        for (int i = 0; i < 4; i++)
            #pragma unroll
            for (int j = 0; j < 8; j++) acc[i][j] = 0ull;

        for (int k0 = 0; k0 < DIM; k0 += 32) {
            float2 xr[4], wr[8];
            #pragma unroll
            for (int r = 0; r < 4; r++) {
                int idx = t + 256 * r;
                int row = idx >> 4, cc = idx & 15;
                xr[r] = *(const float2*)&X[(size_t)(bo + row) * DIM + k0 + 2 * cc];
            }
            #pragma unroll
            for (int r = 0; r < 8; r++) {
                int idx = t + 256 * r;
                int row = idx >> 4, cc = idx & 15;
                wr[r] = *(const float2*)&W[(size_t)(co + row) * DIM + k0 + 2 * cc];
            }
            __syncthreads();
            #pragma unroll
            for (int r = 0; r < 4; r++) {
                int idx = t + 256 * r;
                int row = idx >> 4, cc = idx & 15;
                *(float2*)&xs[row * FB_SST + 2 * cc] = xr[r];
            }
            #pragma unroll
            for (int r = 0; r < 8; r++) {
                int idx = t + 256 * r;
                int row = idx >> 4, cc = idx & 15;
                *(float2*)&ws[row * FB_SST + 2 * cc] = wr[r];
            }
            __syncthreads();

            #pragma unroll
            for (int kp = 0; kp < 16; kp++) {
                u64 a2[4], b2[8];
                #pragma unroll
                for (int i = 0; i < 4; i++)
                    a2[i] = *(const u64*)&xs[(tby + 16 * i) * FB_SST + 2 * kp];
                #pragma unroll
                for (int j = 0; j < 8; j++)
                    b2[j] = *(const u64*)&ws[(tcx + 16 * j) * FB_SST + 2 * kp];
                #pragma unroll
                for (int i = 0; i < 4; i++)
                    #pragma unroll
                    for (int j = 0; j < 8; j++)
                        acc[i][j] = fma2(a2[i], b2[j], acc[i][j]);
            }
        }

        float wnj[8];
        #pragma unroll
        for (int j = 0; j < 8; j++) wnj[j] = g_wn[co + tcx + 16 * j];

        #pragma unroll
        for (int i = 0; i < 4; i++) {
            u64 best = 0ull;
            #pragma unroll
            for (int j = 0; j < 8; j++) {
                float score = lo2(acc[i][j]) + hi2(acc[i][j]) - 0.5f * wnj[j];
                unsigned cidx = (unsigned)(co + tcx + 16 * j);
                u64 key = ((u64)ordf(score) << 32) | (0xFFFFFFFFu - cidx);
                if (key > best) best = key;
            }
            red[tby + 16 * i][tcx] = best;
        }
        __syncthreads();
        if (t < 64) {
            u64 m = red[t][0];
            #pragma unroll
            for (int j = 1; j < 16; j++) {
                u64 v = red[t][j];
                if (v > m) m = v;
            }
            atomicMax(&g_key[bo + t], m);
        }
        __syncthreads();
    }
#endif
}

// decode packed keys -> bmu indices + histogram
__global__ void decode_hist_kernel() {
    int t = blockIdx.x * blockDim.x + threadIdx.x;
    if (t < BS) {
        int idx = (int)(0xFFFFFFFFu - (unsigned)(g_key[t] & 0xFFFFFFFFull));
        g_bmu[t] = idx;
        atomicAdd(&g_hist[idx], 1);
    }
}

// ---------------------------------------------------------------------------
// S[c] via separable convolution of the BMU histogram.
// conv1: T[i][cj] = sum_j H[i][j] * f(|cj-j|)
__global__ void conv1_kernel(const int* __restrict__ itp) {
    __shared__ float sf[128];
    const int t = threadIdx.x;
    const float decay = 1.0f - (float)(*itp) / NITER_F;
    const float sig = SIGMA_F * decay;
    const float inv_s2 = 1.0f / (sig * sig);
    if (t < 128) sf[t] = __expf(-(float)(t * t) * inv_s2);
    __syncthreads();
    int g = blockIdx.x * 256 + t;
    int i = g >> 7, cj = g & 127;
    const int* Hrow = &g_hist[i * 128];
    float s = 0.f;
    #pragma unroll 8
    for (int j = 0; j < 128; j++)
        s = fmaf((float)Hrow[j], sf[::abs(cj - j)], s);
    g_T[g] = s;
}

// conv2: S[ci][cj] = alpha * sum_i f(|ci-i|) * T[i][cj]
__global__ void conv2_kernel(const int* __restrict__ itp) {
    __shared__ float sf[128];
    const int t = threadIdx.x;
    const float decay = 1.0f - (float)(*itp) / NITER_F;
    const float alpha = ALPHA_F * decay;
    const float sig = SIGMA_F * decay;
    const float inv_s2 = 1.0f / (sig * sig);
    if (t < 128) sf[t] = __expf(-(float)(t * t) * inv_s2);
    __syncthreads();
    int g = blockIdx.x * 256 + t;
    int ci = g >> 7, cj = g & 127;
    float s = 0.f;
    #pragma unroll 8
    for (int i = 0; i < 128; i++)
        s = fmaf(sf[::abs(ci - i)], g_T[i * 128 + cj], s);
    g_S[g] = alpha * s;
}

// ---------------------------------------------------------------------------
// K2: update via tcgen05. delta = lr^T X : M=128 c x N=256 d per CTA, K=4096 b.
// out[c,d] = W[c,d]*(1-S[c]) + delta[c,d].
#define UKCH     64
#define UNCH     (BS / UKCH)          // 64 chunks
#define SM_F     256                  // f table (128 floats) within first 1KB
#define UA_HI    1024
#define UA_LO    (UA_HI + 16384)
#define UB       (UA_LO + 16384)      // tile ct: hi at UB+ct*32768, lo +16384
#define SMEM_UPD (UB + 2 * 32768)     // 99328

__global__ __launch_bounds__(256) void upd_mma_kernel(
    const float* __restrict__ X, const float* __restrict__ W,
    const int* __restrict__ itp, float* __restrict__ out) {
    extern __shared__ char smem[];
    const int t  = threadIdx.x;
    const int c0 = blockIdx.x * 128;
    const int d0 = blockIdx.y * 256;

    const float decay = 1.0f - (float)(*itp) / NITER_F;
    const float alpha = ALPHA_F * decay;
    const float sig   = SIGMA_F * decay;
    const float inv_s2 = 1.0f / (sig * sig);

#if HAS_TC
    const uint32_t sb = smem_u32(smem);
    const int wid  = t >> 5;
    const int lane = t & 31;
    float* sf = (float*)(smem + SM_F);

    if (wid == 0) {
        TC_ALLOC(sb + SM_TMEMPTR, 256);
        TC_RELINQ();
    }
    if (t == 0) MBAR_INIT(sb + SM_MBAR, 1);
    if (t < 128) sf[t] = __expf(-(float)(t * t) * inv_s2);
    __syncthreads();
    uint32_t tmem;
    asm volatile("ld.shared.b32 %0, [%1];" : "=r"(tmem) : "r"(sb + SM_TMEMPTR));

    for (int kc = 0; kc < UNCH; kc++) {
        const int b0 = kc * UKCH;

        // ---- A (lr): 128 c rows x 32 b-pairs, generated on the fly ----
        #pragma unroll
        for (int it = 0; it < 16; it++) {
            int e   = t + it * 256;
            int row = e >> 5, pb = e & 31;
            int c  = c0 + row;
            int ci = c >> 7, cj = c & 127;
            int m0 = g_bmu[b0 + 2 * pb];
            int m1 = g_bmu[b0 + 2 * pb + 1];
            float lr0 = alpha * sf[::abs(ci - (m0 >> 7))] * sf[::abs(cj - (m0 & 127))];
            float lr1 = alpha * sf[::abs(ci - (m1 >> 7))] * sf[::abs(cj - (m1 & 127))];
            __nv_bfloat16 h0 = __float2bfloat16(lr0);
            __nv_bfloat16 h1 = __float2bfloat16(lr1);
            float l0f = lr0 - __bfloat162float(h0);
            float l1f = lr1 - __bfloat162float(h1);
            uint32_t hp = ((uint32_t)__bfloat16_as_ushort(h1) << 16) |
                          __bfloat16_as_ushort(h0);
            uint32_t lp = pack_bf16(l0f, l1f);
            int off = row * 128 + pb * 4;
            int sw  = off ^ ((off >> 3) & 0x70);
            *(uint32_t*)(smem + UA_HI + sw) = hp;
            *(uint32_t*)(smem + UA_LO + sw) = lp;
        }
        // ---- B (X^T): 2 tiles x 128 d rows x 8 blocks, hi+lo ----
        #pragma unroll
        for (int it = 0; it < 16; it++) {
            int e = t + it * 256;
            int tp = e >> 10;
            int tile = tp >> 1, pol = tp & 1;
            int idx = e & 1023;
            int row = idx >> 3, blk = idx & 7;
            int dg = d0 + tile * 128 + row;
            uint4 v = (pol ? g_xtl4 : g_xth4)[(size_t)dg * (BS / 8) + b0 / 8 + blk];
            int off = row * 128 + blk * 16;
            int sw  = off ^ ((off >> 3) & 0x70);
            *(uint4*)(smem + UB + tile * 32768 + pol * 16384 + sw) = v;
        }
        FENCE_ASYNC();
        __syncthreads();

        if (wid == 0 && elect_one_pred()) {
            u64 dah = make_desc(sb + UA_HI);
            u64 dal = make_desc(sb + UA_LO);
            #pragma unroll
            for (int ct = 0; ct < 2; ct++) {
                u64 dbh = make_desc(sb + UB + ct * 32768);
                u64 dbl = make_desc(sb + UB + ct * 32768 + 16384);
                uint32_t D = tmem + ct * 128;
                #pragma unroll
                for (int s = 0; s < 4; s++) {
                    mma_f16_ss(D, dah + 2 * s, dbh + 2 * s, BMU_IDESC,
                               !(kc == 0 && s == 0));
                    mma_f16_ss(D, dal + 2 * s, dbh + 2 * s, BMU_IDESC, true);
                    mma_f16_ss(D, dah + 2 * s, dbl + 2 * s, BMU_IDESC, true);
                }
            }
            TC_COMMIT(sb + SM_MBAR);
        }
        mbar_wait(sb + SM_MBAR, (uint32_t)(kc & 1));
    }

    TC_FENCE_AFTER();

    // ---- epilogue: warps 0-3 own the 128 c rows ----
    if (wid < 4) {
        const int c = c0 + wid * 32 + lane;
        const float om = 1.0f - g_S[c];
        #pragma unroll
        for (int ct = 0; ct < 2; ct++) {
            #pragma unroll
            for (int ch = 0; ch < 4; ch++) {
                uint32_t r[32];
                LDTM_X32(r, tmem + ct * 128 + ch * 32);
                TC_WAIT_LD();
                int dbase = d0 + ct * 128 + ch * 32;
                #pragma unroll
                for (int j = 0; j < 32; j++) {
                    size_t o = (size_t)c * DIM + dbase + j;
                    out[o] = fmaf(W[o], om, __uint_as_float(r[j]));
                }
            }
        }
    }

    __syncthreads();
    if (wid == 0) TC_DEALLOC(tmem, 256);

#else  // ---------------- scalar fallback (plain sm_103 cubin; not expected to run)
    float* sf  = (float*)smem;                 // 128 floats
    float* xsf = (float*)(smem + 512);         // 8 x 256
    float* lrf = xsf + 8 * 256;                // 8 x 128

    if (t < 128) sf[t] = __expf(-(float)(t * t) * inv_s2);
    __syncthreads();

    const int cl = t & 127;
    const int dh = t >> 7;          // 0 or 1 -> which 128-d half
    const int c  = c0 + cl;
    const int ci = c >> 7, cj = c & 127;

    float acc[128];
    #pragma unroll
    for (int d = 0; d < 128; d++) acc[d] = 0.f;

    for (int b0 = 0; b0 < BS; b0 += 8) {
        #pragma unroll
        for (int j = 0; j < 8; j++)
            xsf[j * 256 + t] = X[(size_t)(b0 + j) * DIM + d0 + t];
        if (t < 128) {
            #pragma unroll
            for (int j = 0; j < 8; j++) {
                int m = g_bmu[b0 + j];
                lrf[j * 128 + t] =
                    alpha * sf[::abs(ci - (m >> 7))] * sf[::abs(cj - (m & 127))];
            }
        }
        __syncthreads();
        #pragma unroll
        for (int j = 0; j < 8; j++) {
            float l = lrf[j * 128 + cl];
            #pragma unroll
            for (int d = 0; d < 128; d++)
                acc[d] = fmaf(l, xsf[j * 256 + dh * 128 + d], acc[d]);
        }
        __syncthreads();
    }

    const float om = 1.0f - g_S[c];
    #pragma unroll
    for (int d = 0; d < 128; d++) {
        size_t o = (size_t)c * DIM + d0 + dh * 128 + d;
        out[o] = fmaf(W[o], om, acc[d]);
    }
#endif
}

// ---------------------------------------------------------------------------
extern "C" void kernel_launch(void* const* d_in, const int* in_sizes, int n_in,
                              void* d_out, int out_size) {
    const float* X  = (const float*)d_in[0];   // embedded [4096, 768]
    const float* W  = (const float*)d_in[1];   // weights  [16384, 768]
    const int*   it = (const int*)d_in[2];     // scalar it
    float* out = (float*)d_out;                // [16384, 768]

    cudaFuncSetAttribute(bmu_mma_kernel,
                         cudaFuncAttributeMaxDynamicSharedMemorySize, SMEM_BMU);
    cudaFuncSetAttribute(upd_mma_kernel,
                         cudaFuncAttributeMaxDynamicSharedMemorySize, SMEM_UPD);

    prep_kernel<<<COMPS / 256, 256>>>();
    wn_kernel<<<COMPS / 8, 256>>>(W);
    split_w_kernel<<<COMPS * DIM / 8 / 256, 256>>>(W);
    dim3 grid_sx(BS / 32, DIM / 32);
    split_x_t_kernel<<<grid_sx, 256>>>(X);

    dim3 grid_bmu(COMPS / 256, BS / 128);
    bmu_mma_kernel<<<grid_bmu, 256, SMEM_BMU>>>(X, W);
    decode_hist_kernel<<<BS / 256, 256>>>();

    conv1_kernel<<<COMPS / 256, 256>>>(it);
    conv2_kernel<<<COMPS / 256, 256>>>(it);

    dim3 grid_upd(COMPS / 128, DIM / 256);
    upd_mma_kernel<<<grid_upd, 256, SMEM_UPD>>>(X, W, it, out);
}

// round 13
// speedup vs baseline: 8.2281x; 1.4633x over previous
#include <cuda_runtime.h>
#include <cuda_bf16.h>
#include <cstdint>
#include <cstdlib>

// Problem constants (fixed shapes)
#define SOM_M   128
#define SOM_N   128
#define COMPS   16384     // SOM_M * SOM_N
#define BS      4096
#define DIM     768
#define NITER_F 1000.0f
#define ALPHA_F 0.3f
#define SIGMA_F 64.0f     // max(M,N)/2

typedef unsigned long long u64;

// tcgen05 is an arch-specific ('a') feature: only compile it in the sm_103a
// (or sm_100a) pass. The plain compute_103 pass gets scalar fallback bodies
// for the SAME kernel symbols.
#if defined(__CUDA_ARCH_FEAT_SM103_ALL) || defined(__CUDA_ARCH_FEAT_SM100_ALL)
#define HAS_TC 1
#else
#define HAS_TC 0
#endif

// ---------------------------------------------------------------------------
// Device scratch (no allocations allowed in kernel_launch)
__device__ float g_wn[COMPS];
__device__ u64   g_key[BS];
__device__ int   g_bmu[BS];
__device__ int   g_hist[COMPS];     // BMU histogram over the 128x128 grid
__device__ float g_T[COMPS];        // intermediate of separable S-convolution
__device__ float g_S[COMPS];        // S[c] = sum_b lr[b,c]

// Pre-swizzled bf16 hi/lo tile images (exact SW128 SMEM layout, 16KB each):
//   W : tile (ct 0..127, kc 0..11, pol) at ((ct*12+kc)*2+pol)*16384 bytes
//   X : tile (bt 0..31,  kc 0..11, pol)  -- b-major, for BMU A
//   XT: tile (dt 0..5,  ukc 0..63, pol)  -- d-major, for update B
__device__ uint4 g_wsw [128 * 12 * 2 * 1024];   // 50.3 MB
__device__ uint4 g_xsw [ 32 * 12 * 2 * 1024];   // 12.6 MB
__device__ uint4 g_xtsw[  6 * 64 * 2 * 1024];   // 12.6 MB

// ---------------------------------------------------------------------------
// PTX helpers (arch-neutral)
__device__ __forceinline__ uint32_t smem_u32(const void* p) {
    uint32_t a;
    asm("{ .reg .u64 t; cvta.to.shared.u64 t, %1; cvt.u32.u64 %0, t; }"
        : "=r"(a) : "l"(p));
    return a;
}
__device__ __forceinline__ u64 fma2(u64 a, u64 b, u64 c) {
    u64 d;
    asm("fma.rn.f32x2 %0, %1, %2, %3;" : "=l"(d) : "l"(a), "l"(b), "l"(c));
    return d;
}
__device__ __forceinline__ float lo2(u64 v) { return __uint_as_float((unsigned)v); }
__device__ __forceinline__ float hi2(u64 v) { return __uint_as_float((unsigned)(v >> 32)); }

__device__ __forceinline__ unsigned ordf(float f) {
    unsigned u = __float_as_uint(f);
    return (u & 0x80000000u) ? ~u : (u | 0x80000000u);
}

__device__ __forceinline__ uint32_t pack_bf16(float a, float b) {
    return ((uint32_t)__bfloat16_as_ushort(__float2bfloat16(b)) << 16) |
           __bfloat16_as_ushort(__float2bfloat16(a));
}
// split 8 consecutive floats into packed bf16 hi/lo uint4s
__device__ __forceinline__ void split8(const float* v, uint4& hi, uint4& lo) {
    uint32_t h[4], l[4];
    #pragma unroll
    for (int k = 0; k < 4; k++) {
        float a = v[2 * k], b = v[2 * k + 1];
        __nv_bfloat16 ha = __float2bfloat16(a), hb = __float2bfloat16(b);
        float la = a - __bfloat162float(ha);
        float lb = b - __bfloat162float(hb);
        h[k] = ((uint32_t)__bfloat16_as_ushort(hb) << 16) | __bfloat16_as_ushort(ha);
        l[k] = pack_bf16(la, lb);
    }
    hi = make_uint4(h[0], h[1], h[2], h[3]);
    lo = make_uint4(l[0], l[1], l[2], l[3]);
}

#define MBAR_INIT(a, c) asm volatile("mbarrier.init.shared.b64 [%0], %1;" :: "r"(a), "r"(c) : "memory")
#define MBAR_EXPECT_TX(a, bytes) \
    asm volatile("mbarrier.arrive.expect_tx.shared.b64 _, [%0], %1;" :: "r"(a), "r"(bytes) : "memory")
#define FENCE_ASYNC() asm volatile("fence.proxy.async.shared::cta;" ::: "memory")

__device__ __forceinline__ void mbar_wait(uint32_t mb, uint32_t parity) {
    asm volatile(
        "{\n\t"
        ".reg .pred P1;\n\t"
        "WL_%=:\n\t"
        "mbarrier.try_wait.parity.acquire.cta.shared::cta.b64 P1, [%0], %1, 0x989680;\n\t"
        "@P1 bra.uni WD_%=;\n\t"
        "bra.uni WL_%=;\n\t"
        "WD_%=:\n\t"
        "}"
        :: "r"(mb), "r"(parity) : "memory");
}

#if HAS_TC
// --- tcgen05-only helpers ---
static constexpr u64 DESC_BASE_SW128 =
    (u64(2) << 61) | (u64(1) << 46) | (u64(64) << 32) | (u64(1) << 16);
__device__ __forceinline__ u64 make_desc(uint32_t addr) {
    return DESC_BASE_SW128 | ((u64)(addr >> 4) & 0x3FFF);
}

__device__ __forceinline__ void mma_f16_ss(uint32_t d_tmem, u64 a_desc, u64 b_desc,
                                           uint32_t idesc, bool en_d) {
    uint32_t en = en_d ? 1u : 0u;
    asm volatile(
        "{\n\t"
        ".reg .pred p;\n\t"
        "setp.ne.u32 p, %5, 0;\n\t"
        "tcgen05.mma.cta_group::1.kind::f16 [%0], %1, %2, %3, {%4,%4,%4,%4}, p;\n\t"
        "}"
        :: "r"(d_tmem), "l"(a_desc), "l"(b_desc), "r"(idesc), "r"(0u), "r"(en)
        : "memory");
}

// single-instruction bulk copy global -> SMEM with mbarrier complete_tx
__device__ __forceinline__ void bulk_cp(uint32_t dst, const void* src,
                                        uint32_t bytes, uint32_t mbar) {
    asm volatile(
        "cp.async.bulk.shared::cta.global.mbarrier::complete_tx::bytes "
        "[%0], [%1], %2, [%3];"
        :: "r"(dst), "l"(src), "r"(bytes), "r"(mbar) : "memory");
}

#define TC_ALLOC(sa, n)   asm volatile("tcgen05.alloc.cta_group::1.sync.aligned.shared::cta.b32 [%0], %1;" :: "r"(sa), "r"(n) : "memory")
#define TC_DEALLOC(tm, n) asm volatile("tcgen05.dealloc.cta_group::1.sync.aligned.b32 %0, %1;" :: "r"(tm), "r"(n))
#define TC_RELINQ()       asm volatile("tcgen05.relinquish_alloc_permit.cta_group::1.sync.aligned;")
#define TC_COMMIT(mb)     asm volatile("tcgen05.commit.cta_group::1.mbarrier::arrive::one.shared::cluster.b64 [%0];" :: "r"(mb) : "memory")
#define TC_FENCE_AFTER()  asm volatile("tcgen05.fence::after_thread_sync;" ::: "memory")
#define TC_WAIT_LD()      asm volatile("tcgen05.wait::ld.sync.aligned;" ::: "memory")

#define LDTM_X32(r, ta) \
    asm volatile( \
        "tcgen05.ld.sync.aligned.32x32b.x32.b32 " \
        "{%0,%1,%2,%3,%4,%5,%6,%7,%8,%9,%10,%11,%12,%13,%14,%15," \
        "%16,%17,%18,%19,%20,%21,%22,%23,%24,%25,%26,%27,%28,%29,%30,%31}, [%32];" \
        : "=r"((r)[0]),"=r"((r)[1]),"=r"((r)[2]),"=r"((r)[3]), \
          "=r"((r)[4]),"=r"((r)[5]),"=r"((r)[6]),"=r"((r)[7]), \
          "=r"((r)[8]),"=r"((r)[9]),"=r"((r)[10]),"=r"((r)[11]), \
          "=r"((r)[12]),"=r"((r)[13]),"=r"((r)[14]),"=r"((r)[15]), \
          "=r"((r)[16]),"=r"((r)[17]),"=r"((r)[18]),"=r"((r)[19]), \
          "=r"((r)[20]),"=r"((r)[21]),"=r"((r)[22]),"=r"((r)[23]), \
          "=r"((r)[24]),"=r"((r)[25]),"=r"((r)[26]),"=r"((r)[27]), \
          "=r"((r)[28]),"=r"((r)[29]),"=r"((r)[30]),"=r"((r)[31]) \
        : "r"(ta))
#endif  // HAS_TC

// ---------------------------------------------------------------------------
// K0: zero keys + histogram
__global__ void prep_kernel() {
    int t = blockIdx.x * blockDim.x + threadIdx.x;
    if (t < COMPS) g_hist[t] = 0;
    if (t < BS)    g_key[t]  = 0ull;
}

// K0b: wn[c] = ||w_c||^2  (one warp per row)
__global__ void wn_kernel(const float* __restrict__ W) {
    int warp = threadIdx.x >> 5;
    int lane = threadIdx.x & 31;
    int c = blockIdx.x * 8 + warp;
    if (c >= COMPS) return;
    const float* row = &W[(size_t)c * DIM];
    float s = 0.f;
    #pragma unroll 6
    for (int i = lane; i < DIM; i += 32) {
        float v = row[i];
        s = fmaf(v, v, s);
    }
    #pragma unroll
    for (int o = 16; o > 0; o >>= 1) s += __shfl_xor_sync(0xFFFFFFFFu, s, o);
    if (lane == 0) g_wn[c] = s;
}

// K0c: W fp32 -> pre-swizzled bf16 hi/lo tile images
__global__ void split_w_kernel(const float* __restrict__ W) {
    int idx = blockIdx.x * blockDim.x + threadIdx.x;   // one uint4 (8 elems)
    if (idx >= COMPS * DIM / 8) return;
    int c  = idx / 96;           // 96 uint4 per W row
    int g  = idx % 96;
    int kc = g >> 3, blk = g & 7;
    float v[8];
    const float4* p = (const float4*)(W + (size_t)c * DIM + kc * 64 + blk * 8);
    float4 a = p[0], b = p[1];
    v[0]=a.x; v[1]=a.y; v[2]=a.z; v[3]=a.w;
    v[4]=b.x; v[5]=b.y; v[6]=b.z; v[7]=b.w;
    uint4 hi, lo;
    split8(v, hi, lo);
    int ct = c >> 7, r = c & 127;
    int off = r * 128 + blk * 16;
    int sw  = off ^ ((off >> 3) & 0x70);
    size_t base = (size_t)((ct * 12 + kc) * 2) * 16384;
    *(uint4*)((char*)g_wsw + base + sw)         = hi;
    *(uint4*)((char*)g_wsw + base + 16384 + sw) = lo;
}

// K0d: X -> pre-swizzled bf16 hi/lo, both b-major (BMU A) and d-major (upd B)
__global__ void split_x_t_kernel(const float* __restrict__ X) {
    __shared__ float tile[32][33];
    const int t  = threadIdx.x;
    const int tx = t & 31, ty = t >> 5;       // 8 rows per pass
    const int b0 = blockIdx.x * 32;
    const int d0 = blockIdx.y * 32;

    #pragma unroll
    for (int i = 0; i < 4; i++)
        tile[ty + 8 * i][tx] = X[(size_t)(b0 + ty + 8 * i) * DIM + d0 + tx];
    __syncthreads();

    if (t < 128) {
        // b-major (BMU A image)
        int brow = t >> 2, blk = t & 3;
        float v[8];
        #pragma unroll
        for (int k = 0; k < 8; k++) v[k] = tile[brow][blk * 8 + k];
        uint4 hi, lo;
        split8(v, hi, lo);
        int b = b0 + brow, d = d0 + blk * 8;
        int bt = b >> 7, r = b & 127;
        int kc = d >> 6, kblk = (d >> 3) & 7;
        int off = r * 128 + kblk * 16;
        int sw  = off ^ ((off >> 3) & 0x70);
        size_t base = (size_t)((bt * 12 + kc) * 2) * 16384;
        *(uint4*)((char*)g_xsw + base + sw)         = hi;
        *(uint4*)((char*)g_xsw + base + 16384 + sw) = lo;
    } else {
        // d-major (update B image)
        int t2 = t - 128;
        int drow = t2 >> 2, blkb = t2 & 3;
        float v[8];
        #pragma unroll
        for (int k = 0; k < 8; k++) v[k] = tile[blkb * 8 + k][drow];
        uint4 hi, lo;
        split8(v, hi, lo);
        int b = b0 + blkb * 8, d = d0 + drow;
        int ukc = b >> 6, bblk = (b >> 3) & 7;
        int dt = d >> 7, r = d & 127;
        int off = r * 128 + bblk * 16;
        int sw  = off ^ ((off >> 3) & 0x70);
        size_t base = (size_t)((dt * 64 + ukc) * 2) * 16384;
        *(uint4*)((char*)g_xtsw + base + sw)         = hi;
        *(uint4*)((char*)g_xtsw + base + 16384 + sw) = lo;
    }
}

// ---------------------------------------------------------------------------
// K1: BMU. CTA tile 128 b x 256 c; tcgen05 bf16-split; staging via cp.async.bulk
// from pre-swizzled images.
#define KCH      64
#define NCHUNKS  (DIM / KCH)          // 12
#define BMU_IDESC ((1u<<4) | (1u<<7) | (1u<<10) | ((128u/8)<<17) | ((128u/16)<<24))

#define SM_TMEMPTR 0
#define SM_MBAR    8                  // mma-done mbarrier
#define SM_CPBAR   16                 // copy-done mbarrier
#define SM_F       256                // f table (update kernel only)
#define SM_A_HI    1024
#define SM_A_LO    (SM_A_HI + 16384)
#define SM_BH      (SM_A_LO + 16384)
#define SMEM_BMU   (SM_BH + 2 * 32768)       // 99328

__global__ __launch_bounds__(256, 2) void bmu_mma_kernel(const float* __restrict__ X,
                                                         const float* __restrict__ W) {
    extern __shared__ char smem[];
    const int t  = threadIdx.x;
    const int c0 = blockIdx.x * 256;
    const int b0 = blockIdx.y * 128;

#if HAS_TC
    const uint32_t sb = smem_u32(smem);
    const int wid  = t >> 5;
    const int lane = t & 31;
    const int bt   = blockIdx.y;
    const int ct0  = blockIdx.x * 2;

    if (wid == 0) {
        TC_ALLOC(sb + SM_TMEMPTR, 256);
        TC_RELINQ();
    }
    if (t == 0) {
        MBAR_INIT(sb + SM_MBAR, 1);
        MBAR_INIT(sb + SM_CPBAR, 1);
    }
    __syncthreads();
    uint32_t tmem;
    asm volatile("ld.shared.b32 %0, [%1];" : "=r"(tmem) : "r"(sb + SM_TMEMPTR));

    for (int kc = 0; kc < NCHUNKS; kc++) {
        // all threads: MMA of chunk kc-1 must be done before buffers reload
        if (kc > 0) mbar_wait(sb + SM_MBAR, (uint32_t)((kc - 1) & 1));

        if (t == 0) {
            MBAR_EXPECT_TX(sb + SM_CPBAR, 6 * 16384);
            const char* xb = (const char*)g_xsw +
                             (size_t)((bt * 12 + kc) * 2) * 16384;
            bulk_cp(sb + SM_A_HI, xb,         16384, sb + SM_CPBAR);
            bulk_cp(sb + SM_A_LO, xb + 16384, 16384, sb + SM_CPBAR);
            #pragma unroll
            for (int ct = 0; ct < 2; ct++) {
                const char* wb = (const char*)g_wsw +
                                 (size_t)(((ct0 + ct) * 12 + kc) * 2) * 16384;
                bulk_cp(sb + SM_BH + ct * 32768,         wb,         16384, sb + SM_CPBAR);
                bulk_cp(sb + SM_BH + ct * 32768 + 16384, wb + 16384, 16384, sb + SM_CPBAR);
            }
            mbar_wait(sb + SM_CPBAR, (uint32_t)(kc & 1));

            u64 dah = make_desc(sb + SM_A_HI);
            u64 dal = make_desc(sb + SM_A_LO);
            #pragma unroll
            for (int ct = 0; ct < 2; ct++) {
                u64 dbh = make_desc(sb + SM_BH + ct * 32768);
                u64 dbl = make_desc(sb + SM_BH + ct * 32768 + 16384);
                uint32_t D = tmem + ct * 128;
                #pragma unroll
                for (int s = 0; s < 4; s++) {
                    mma_f16_ss(D, dah + 2 * s, dbh + 2 * s, BMU_IDESC,
                               !(kc == 0 && s == 0));
                    mma_f16_ss(D, dal + 2 * s, dbh + 2 * s, BMU_IDESC, true);
                    mma_f16_ss(D, dah + 2 * s, dbl + 2 * s, BMU_IDESC, true);
                }
            }
            TC_COMMIT(sb + SM_MBAR);
        }
    }
    // final MMA completion
    mbar_wait(sb + SM_MBAR, (uint32_t)((NCHUNKS - 1) & 1));
    TC_FENCE_AFTER();

    if (wid < 4) {
        const int b = b0 + wid * 32 + lane;
        u64 best = 0ull;
        #pragma unroll
        for (int ct = 0; ct < 2; ct++) {
            #pragma unroll
            for (int ch = 0; ch < 4; ch++) {
                uint32_t r[32];
                LDTM_X32(r, tmem + ct * 128 + ch * 32);
                TC_WAIT_LD();
                int cbase = c0 + ct * 128 + ch * 32;
                #pragma unroll
                for (int j = 0; j < 32; j++) {
                    float score = __uint_as_float(r[j]) - 0.5f * g_wn[cbase + j];
                    u64 key = ((u64)ordf(score) << 32) |
                              (0xFFFFFFFFu - (unsigned)(cbase + j));
                    if (key > best) best = key;
                }
            }
        }
        atomicMax(&g_key[b], best);
    }

    __syncthreads();
    if (wid == 0) TC_DEALLOC(tmem, 256);

#else  // ---------------- scalar f32x2 fallback (plain sm_103 cubin) --------
    #define FB_SST 34
    float* xs = (float*)smem;
    float* ws = (float*)(smem + 64 * FB_SST * 4);
    u64 (*red)[16] = (u64(*)[16])(smem + (64 + 128) * FB_SST * 4);

    const int tby = t >> 4;
    const int tcx = t & 15;

    for (int pass = 0; pass < 4; pass++) {
        const int bo = b0 + (pass >> 1) * 64;
        const int co = c0 + (pass & 1) * 128;

        u64 acc[4][8];
        #pragma unroll
        for (int i = 0; i < 4; i++)
            #pragma unroll
            for (int j = 0; j < 8; j++) acc[i][j] = 0ull;

        for (int k0 = 0; k0 < DIM; k0 += 32) {
            float2 xr[4], wr[8];
            #pragma unroll
            for (int r = 0; r < 4; r++) {
                int idx = t + 256 * r;
                int row = idx >> 4, cc = idx & 15;
                xr[r] = *(const float2*)&X[(size_t)(bo + row) * DIM + k0 + 2 * cc];
            }
            #pragma unroll
            for (int r = 0; r < 8; r++) {
                int idx = t + 256 * r;
                int row = idx >> 4, cc = idx & 15;
                wr[r] = *(const float2*)&W[(size_t)(co + row) * DIM + k0 + 2 * cc];
            }
            __syncthreads();
            #pragma unroll
            for (int r = 0; r < 4; r++) {
                int idx = t + 256 * r;
                int row = idx >> 4, cc = idx & 15;
                *(float2*)&xs[row * FB_SST + 2 * cc] = xr[r];
            }
            #pragma unroll
            for (int r = 0; r < 8; r++) {
                int idx = t + 256 * r;
                int row = idx >> 4, cc = idx & 15;
                *(float2*)&ws[row * FB_SST + 2 * cc] = wr[r];
            }
            __syncthreads();

            #pragma unroll
            for (int kp = 0; kp < 16; kp++) {
                u64 a2[4], b2[8];
                #pragma unroll
                for (int i = 0; i < 4; i++)
                    a2[i] = *(const u64*)&xs[(tby + 16 * i) * FB_SST + 2 * kp];
                #pragma unroll
                for (int j = 0; j < 8; j++)
                    b2[j] = *(const u64*)&ws[(tcx + 16 * j) * FB_SST + 2 * kp];
                #pragma unroll
                for (int i = 0; i < 4; i++)
                    #pragma unroll
                    for (int j = 0; j < 8; j++)
                        acc[i][j] = fma2(a2[i], b2[j], acc[i][j]);
            }
        }

        float wnj[8];
        #pragma unroll
        for (int j = 0; j < 8; j++) wnj[j] = g_wn[co + tcx + 16 * j];

        #pragma unroll
        for (int i = 0; i < 4; i++) {
            u64 best = 0ull;
            #pragma unroll
            for (int j = 0; j < 8; j++) {
                float score = lo2(acc[i][j]) + hi2(acc[i][j]) - 0.5f * wnj[j];
                unsigned cidx = (unsigned)(co + tcx + 16 * j);
                u64 key = ((u64)ordf(score) << 32) | (0xFFFFFFFFu - cidx);
                if (key > best) best = key;
            }
            red[tby + 16 * i][tcx] = best;
        }
        __syncthreads();
        if (t < 64) {
            u64 m = red[t][0];
            #pragma unroll
            for (int j = 1; j < 16; j++) {
                u64 v = red[t][j];
                if (v > m) m = v;
            }
            atomicMax(&g_key[bo + t], m);
        }
        __syncthreads();
    }
#endif
}

// decode packed keys -> bmu indices + histogram
__global__ void decode_hist_kernel() {
    int t = blockIdx.x * blockDim.x + threadIdx.x;
    if (t < BS) {
        int idx = (int)(0xFFFFFFFFu - (unsigned)(g_key[t] & 0xFFFFFFFFull));
        g_bmu[t] = idx;
        atomicAdd(&g_hist[idx], 1);
    }
}

// ---------------------------------------------------------------------------
// S[c] via separable convolution of the BMU histogram.
__global__ void conv1_kernel(const int* __restrict__ itp) {
    __shared__ float sf[128];
    const int t = threadIdx.x;
    const float decay = 1.0f - (float)(*itp) / NITER_F;
    const float sig = SIGMA_F * decay;
    const float inv_s2 = 1.0f / (sig * sig);
    if (t < 128) sf[t] = __expf(-(float)(t * t) * inv_s2);
    __syncthreads();
    int g = blockIdx.x * 256 + t;
    int i = g >> 7, cj = g & 127;
    const int* Hrow = &g_hist[i * 128];
    float s = 0.f;
    #pragma unroll 8
    for (int j = 0; j < 128; j++)
        s = fmaf((float)Hrow[j], sf[::abs(cj - j)], s);
    g_T[g] = s;
}

__global__ void conv2_kernel(const int* __restrict__ itp) {
    __shared__ float sf[128];
    const int t = threadIdx.x;
    const float decay = 1.0f - (float)(*itp) / NITER_F;
    const float alpha = ALPHA_F * decay;
    const float sig = SIGMA_F * decay;
    const float inv_s2 = 1.0f / (sig * sig);
    if (t < 128) sf[t] = __expf(-(float)(t * t) * inv_s2);
    __syncthreads();
    int g = blockIdx.x * 256 + t;
    int ci = g >> 7, cj = g & 127;
    float s = 0.f;
    #pragma unroll 8
    for (int i = 0; i < 128; i++)
        s = fmaf(sf[::abs(ci - i)], g_T[i * 128 + cj], s);
    g_S[g] = alpha * s;
}

// ---------------------------------------------------------------------------
// K2: update via tcgen05. delta = lr^T X : M=128 c x N=256 d per CTA, K=4096 b.
// A (lr) generated in SMEM; B (X^T) via cp.async.bulk from pre-swizzled image.
#define UKCH     64
#define UNCH     (BS / UKCH)          // 64 chunks
#define UA_HI    1024
#define UA_LO    (UA_HI + 16384)
#define UB       (UA_LO + 16384)
#define SMEM_UPD (UB + 2 * 32768)     // 99328

__global__ __launch_bounds__(256, 2) void upd_mma_kernel(
    const float* __restrict__ X, const float* __restrict__ W,
    const int* __restrict__ itp, float* __restrict__ out) {
    extern __shared__ char smem[];
    const int t  = threadIdx.x;
    const int c0 = blockIdx.x * 128;
    const int d0 = blockIdx.y * 256;

    const float decay = 1.0f - (float)(*itp) / NITER_F;
    const float alpha = ALPHA_F * decay;
    const float sig   = SIGMA_F * decay;
    const float inv_s2 = 1.0f / (sig * sig);

#if HAS_TC
    const uint32_t sb = smem_u32(smem);
    const int wid  = t >> 5;
    const int lane = t & 31;
    const int dt0  = blockIdx.y * 2;
    float* sf = (float*)(smem + SM_F);

    if (wid == 0) {
        TC_ALLOC(sb + SM_TMEMPTR, 256);
        TC_RELINQ();
    }
    if (t == 0) {
        MBAR_INIT(sb + SM_MBAR, 1);
        MBAR_INIT(sb + SM_CPBAR, 1);
    }
    if (t < 128) sf[t] = __expf(-(float)(t * t) * inv_s2);
    __syncthreads();
    uint32_t tmem;
    asm volatile("ld.shared.b32 %0, [%1];" : "=r"(tmem) : "r"(sb + SM_TMEMPTR));

    for (int kc = 0; kc < UNCH; kc++) {
        const int b0 = kc * UKCH;
        // MMA of chunk kc-1 must be done before A/B buffers are reloaded
        if (kc > 0) mbar_wait(sb + SM_MBAR, (uint32_t)((kc - 1) & 1));

        // B copies first (overlap with A generation)
        if (t == 0) {
            MBAR_EXPECT_TX(sb + SM_CPBAR, 4 * 16384);
            #pragma unroll
            for (int ct = 0; ct < 2; ct++) {
                const char* xb = (const char*)g_xtsw +
                                 (size_t)(((dt0 + ct) * 64 + kc) * 2) * 16384;
                bulk_cp(sb + UB + ct * 32768,         xb,         16384, sb + SM_CPBAR);
                bulk_cp(sb + UB + ct * 32768 + 16384, xb + 16384, 16384, sb + SM_CPBAR);
            }
        }

        // ---- A (lr): 128 c rows x 32 b-pairs, generated on the fly ----
        #pragma unroll
        for (int it = 0; it < 16; it++) {
            int e   = t + it * 256;
            int row = e >> 5, pb = e & 31;
            int c  = c0 + row;
            int ci = c >> 7, cj = c & 127;
            int m0 = g_bmu[b0 + 2 * pb];
            int m1 = g_bmu[b0 + 2 * pb + 1];
            float lr0 = alpha * sf[::abs(ci - (m0 >> 7))] * sf[::abs(cj - (m0 & 127))];
            float lr1 = alpha * sf[::abs(ci - (m1 >> 7))] * sf[::abs(cj - (m1 & 127))];
            __nv_bfloat16 h0 = __float2bfloat16(lr0);
            __nv_bfloat16 h1 = __float2bfloat16(lr1);
            float l0f = lr0 - __bfloat162float(h0);
            float l1f = lr1 - __bfloat162float(h1);
            uint32_t hp = ((uint32_t)__bfloat16_as_ushort(h1) << 16) |
                          __bfloat16_as_ushort(h0);
            uint32_t lp = pack_bf16(l0f, l1f);
            int off = row * 128 + pb * 4;
            int sw  = off ^ ((off >> 3) & 0x70);
            *(uint32_t*)(smem + UA_HI + sw) = hp;
            *(uint32_t*)(smem + UA_LO + sw) = lp;
        }
        FENCE_ASYNC();
        __syncthreads();

        if (t == 0) {
            mbar_wait(sb + SM_CPBAR, (uint32_t)(kc & 1));
            u64 dah = make_desc(sb + UA_HI);
            u64 dal = make_desc(sb + UA_LO);
            #pragma unroll
            for (int ct = 0; ct < 2; ct++) {
                u64 dbh = make_desc(sb + UB + ct * 32768);
                u64 dbl = make_desc(sb + UB + ct * 32768 + 16384);
                uint32_t D = tmem + ct * 128;
                #pragma unroll
                for (int s = 0; s < 4; s++) {
                    mma_f16_ss(D, dah + 2 * s, dbh + 2 * s, BMU_IDESC,
                               !(kc == 0 && s == 0));
                    mma_f16_ss(D, dal + 2 * s, dbh + 2 * s, BMU_IDESC, true);
                    mma_f16_ss(D, dah + 2 * s, dbl + 2 * s, BMU_IDESC, true);
                }
            }
            TC_COMMIT(sb + SM_MBAR);
        }
    }
    mbar_wait(sb + SM_MBAR, (uint32_t)((UNCH - 1) & 1));
    TC_FENCE_AFTER();

    // ---- epilogue: warps 0-3 own the 128 c rows ----
    if (wid < 4) {
        const int c = c0 + wid * 32 + lane;
        const float om = 1.0f - g_S[c];
        #pragma unroll
        for (int ct = 0; ct < 2; ct++) {
            #pragma unroll
            for (int ch = 0; ch < 4; ch++) {
                uint32_t r[32];
                LDTM_X32(r, tmem + ct * 128 + ch * 32);
                TC_WAIT_LD();
                int dbase = d0 + ct * 128 + ch * 32;
                #pragma unroll
                for (int j = 0; j < 32; j++) {
                    size_t o = (size_t)c * DIM + dbase + j;
                    out[o] = fmaf(W[o], om, __uint_as_float(r[j]));
                }
            }
        }
    }

    __syncthreads();
    if (wid == 0) TC_DEALLOC(tmem, 256);

#else  // ---------------- scalar fallback (plain sm_103 cubin) --------------
    float* sf  = (float*)smem;                 // 128 floats
    float* xsf = (float*)(smem + 512);         // 8 x 256
    float* lrf = xsf + 8 * 256;                // 8 x 128

    if (t < 128) sf[t] = __expf(-(float)(t * t) * inv_s2);
    __syncthreads();

    const int cl = t & 127;
    const int dh = t >> 7;
    const int c  = c0 + cl;
    const int ci = c >> 7, cj = c & 127;

    float acc[128];
    #pragma unroll
    for (int d = 0; d < 128; d++) acc[d] = 0.f;

    for (int b0 = 0; b0 < BS; b0 += 8) {
        #pragma unroll
        for (int j = 0; j < 8; j++)
            xsf[j * 256 + t] = X[(size_t)(b0 + j) * DIM + d0 + t];
        if (t < 128) {
            #pragma unroll
            for (int j = 0; j < 8; j++) {
                int m = g_bmu[b0 + j];
                lrf[j * 128 + t] =
                    alpha * sf[::abs(ci - (m >> 7))] * sf[::abs(cj - (m & 127))];
            }
        }
        __syncthreads();
        #pragma unroll
        for (int j = 0; j < 8; j++) {
            float l = lrf[j * 128 + cl];
            #pragma unroll
            for (int d = 0; d < 128; d++)
                acc[d] = fmaf(l, xsf[j * 256 + dh * 128 + d], acc[d]);
        }
        __syncthreads();
    }

    const float om = 1.0f - g_S[c];
    #pragma unroll
    for (int d = 0; d < 128; d++) {
        size_t o = (size_t)c * DIM + d0 + dh * 128 + d;
        out[o] = fmaf(W[o], om, acc[d]);
    }
#endif
}

// ---------------------------------------------------------------------------
extern "C" void kernel_launch(void* const* d_in, const int* in_sizes, int n_in,
                              void* d_out, int out_size) {
    const float* X  = (const float*)d_in[0];   // embedded [4096, 768]
    const float* W  = (const float*)d_in[1];   // weights  [16384, 768]
    const int*   it = (const int*)d_in[2];     // scalar it
    float* out = (float*)d_out;                // [16384, 768]

    cudaFuncSetAttribute(bmu_mma_kernel,
                         cudaFuncAttributeMaxDynamicSharedMemorySize, SMEM_BMU);
    cudaFuncSetAttribute(upd_mma_kernel,
                         cudaFuncAttributeMaxDynamicSharedMemorySize, SMEM_UPD);

    prep_kernel<<<COMPS / 256, 256>>>();
    wn_kernel<<<COMPS / 8, 256>>>(W);
    split_w_kernel<<<COMPS * DIM / 8 / 256, 256>>>(W);
    dim3 grid_sx(BS / 32, DIM / 32);
    split_x_t_kernel<<<grid_sx, 256>>>(X);

    dim3 grid_bmu(COMPS / 256, BS / 128);
    bmu_mma_kernel<<<grid_bmu, 256, SMEM_BMU>>>(X, W);
    decode_hist_kernel<<<BS / 256, 256>>>();

    conv1_kernel<<<COMPS / 256, 256>>>(it);
    conv2_kernel<<<COMPS / 256, 256>>>(it);

    dim3 grid_upd(COMPS / 128, DIM / 256);
    upd_mma_kernel<<<grid_upd, 256, SMEM_UPD>>>(X, W, it, out);
}